// round 15
// baseline (speedup 1.0000x reference)
#include <cuda_runtime.h>
#include <cuda_bf16.h>
#include <cuda_fp16.h>
#include <cstdint>
#include <math.h>

#define DIMX     128
#define HID      512
#define NSTEPS_  20
#define BATCH_   16384
#define OUTC     131
#define NTHREADS 512
#define NTILES   (BATCH_ / 128)      // 128 CTAs, one M=128 tile each

// ---- arch-specific feature gate (tcgen05 needs sm_10xa target) ----
#if defined(__CUDA_ARCH__)
#  if defined(__CUDA_ARCH_FEAT_SM103_ALL) || defined(__CUDA_ARCH_FEAT_SM100_ALL) || \
      (defined(__CUDA_ARCH_SPECIFIC__) && (__CUDA_ARCH_SPECIFIC__ == 1000 || \
       __CUDA_ARCH_SPECIFIC__ == 1010 || __CUDA_ARCH_SPECIFIC__ == 1030))
#    define HAS_TCGEN05 1
#  else
#    define HAS_TCGEN05 0
#  endif
#else
#  define HAS_TCGEN05 0
#endif

// ---- smem layout for tcgen05 path (bytes) ----
// fp16 [128][128] blocked-atom image = 32768 B.
#define MBAR1A_OFF 0
#define MBAR2_OFF  8
#define TPTR_OFF   16
#define MBW2_OFF   24
#define MBW1_OFF   32
#define MBAR1B_OFF 40
#define PUDW_OFF   1024              // 512 floats [1024,3072)
#define PEN_OFF    3072              // 512 floats [3072,5120)
#define B1EFF_OFF  5120              // 512 floats [5120,7168)
#define B2S_OFF    7168              // 128 floats [7168,7680)
#define H_OFF      8192              // Hhi 32KB, Hlo +32768  -> [8192,73728)
#define W1_OFF     73728             // W1 slot0 32KB -> [73728,106496)
#define W2_OFF     106496            // W2 image 32KB -> [106496,139264)
#define OUTBUF_OFF 139264            // epilogue OUTBUF 64KB; first 32KB doubles
                                     // as W1 slot1 (chunks 1/3) during GEMMs
#define SMEM_BYTES 204800
// epilogue NOISE overlays the H region EXACTLY: [8192,73728) = 65536 B,
// pitch 128 + odd rotation, per-element NB_IDX on both sides.
#define NOISE_OFF  H_OFF
#define NB_IDX(r, c) ((r) * 128 + (((c) + 5 * (r)) & 127))
#define OB_IDX(r, c) ((r) * 128 + (((c) + 5 * (r)) & 127))

// TMEM column offsets (512 total)
#define T_XHI  0
#define T_XLO  64
#define T_D1   128
#define T_U    256
#define T_Y    384

// ---- smem layout for SIMT fallback (floats) ----
#define F_XT    0                    // [129][132]
#define F_W1    17028                // [129][64]
#define F_HT    25284                // [64][132]
#define F_W2    33732                // [64][128]
#define F_B1    41924                // 512
#define F_B2    42436                // 128
#define F_PITCH 132

// ---- device scratch (no allocs allowed) ----
__device__ __align__(128) unsigned char g_w1img[4 * 32768];   // fp16 per chunk
__device__ __align__(128) unsigned char g_w2img[4 * 32768];   // fp16 per chunk
__device__ float g_b1eff[NSTEPS_ * HID];

// =========================== common helpers ===========================
__device__ __forceinline__ uint32_t smem_to_u32(const void* p) {
    uint32_t a;
    asm("{ .reg .u64 t; cvta.to.shared.u64 t, %1; cvt.u32.u64 %0, t; }" : "=r"(a) : "l"(p));
    return a;
}
#define SMEM_SWIZZLE_128B(b) ((b) ^ (((b) >> 3) & 0x70))

// blocked-atom SW128 image byte offset for [row][k] in a [128][128] fp16 tile
__device__ __forceinline__ int img_off(int row, int k) {
    int byte = ((row >> 3) + (k >> 6) * 16) * 1024 + (row & 7) * 128 + (k & 63) * 2;
    return SMEM_SWIZZLE_128B(byte);
}

typedef unsigned long long u64;
__device__ __forceinline__ u64 pack2f(float lo, float hi) {
    u64 r; asm("mov.b64 %0, {%1, %2};" : "=l"(r) : "f"(lo), "f"(hi)); return r;
}
__device__ __forceinline__ u64 fma2(u64 a, u64 b, u64 c) {
    u64 d; asm("fma.rn.f32x2 %0, %1, %2, %3;" : "=l"(d) : "l"(a), "l"(b), "l"(c)); return d;
}
__device__ __forceinline__ float2 unpack2f(u64 v) {
    float2 f; asm("mov.b64 {%0, %1}, %2;" : "=f"(f.x), "=f"(f.y) : "l"(v)); return f;
}

// fast tanh: tanh(x) = 1 - 2/(exp(2x)+1); MUFU ex2 + MUFU rcp, exact saturation
__device__ __forceinline__ float fast_tanh(float x) {
    float e, r;
    asm("ex2.approx.ftz.f32 %0, %1;" : "=f"(e) : "f"(x * 2.8853900817779268f));
    asm("rcp.approx.ftz.f32 %0, %1;" : "=f"(r) : "f"(e + 1.0f));
    return fmaf(-2.0f, r, 1.0f);
}

// fp16 hi/lo split of two floats -> packed half2 words
__device__ __forceinline__ void fp16_split2(float a, float b, uint32_t& hi, uint32_t& lo) {
    __half2 hp = __floats2half2_rn(a, b);
    float ra = a - __half2float(__low2half(hp));
    float rb = b - __half2float(__high2half(hp));
    __half2 lp = __floats2half2_rn(ra, rb);
    hi = *(uint32_t*)&hp;
    lo = *(uint32_t*)&lp;
}

#if HAS_TCGEN05
// =========================== tcgen05 helpers ===========================
__device__ __forceinline__ uint32_t elect_one_pred() {
    uint32_t pred;
    asm volatile("{\n\t.reg .pred p;\n\telect.sync _|p, 0xFFFFFFFF;\n\t"
                 "selp.b32 %0, 1, 0, p;\n\t}" : "=r"(pred));
    return pred;
}
static constexpr uint64_t SMEM_DESC_BASE_SW128 =
    (uint64_t(2) << 61) | (uint64_t(1) << 46) | (uint64_t(64) << 32) | (uint64_t(1) << 16);
#define MAKE_SMEM_DESC(addr) (SMEM_DESC_BASE_SW128 | ((uint64_t)((addr) >> 4) & 0x3FFF))

#define MBARRIER_INIT(a, n) \
    asm volatile("mbarrier.init.shared.b64 [%0], %1;" :: "r"((uint32_t)(a)), "r"((uint32_t)(n)) : "memory")
#define MBARRIER_INVAL(a) \
    asm volatile("mbarrier.inval.shared.b64 [%0];" :: "r"((uint32_t)(a)) : "memory")
#define MBARRIER_EXPECT_TX(a, bytes) \
    asm volatile("mbarrier.arrive.expect_tx.shared.b64 _, [%0], %1;" \
                 :: "r"((uint32_t)(a)), "r"((uint32_t)(bytes)) : "memory")
#define BULK_COPY_G2S(dst, src, bytes, mbar) \
    asm volatile("cp.async.bulk.shared::cta.global.mbarrier::complete_tx::bytes [%0], [%1], %2, [%3];" \
                 :: "r"((uint32_t)(dst)), "l"(src), "r"((uint32_t)(bytes)), "r"((uint32_t)(mbar)) : "memory")
#define TCGEN05_ALLOC(sa, n) \
    asm volatile("tcgen05.alloc.cta_group::1.sync.aligned.shared::cta.b32 [%0], %1;" \
                 :: "r"((uint32_t)(sa)), "r"((uint32_t)(n)) : "memory")
#define TCGEN05_DEALLOC(t, n) \
    asm volatile("tcgen05.dealloc.cta_group::1.sync.aligned.b32 %0, %1;" :: "r"(t), "r"((uint32_t)(n)))
#define TCGEN05_COMMIT(a) \
    asm volatile("tcgen05.commit.cta_group::1.mbarrier::arrive::one.shared::cluster.b64 [%0];" \
                 :: "r"((uint32_t)(a)) : "memory")
#define TCGEN05_WAIT_LD()  asm volatile("tcgen05.wait::ld.sync.aligned;" ::: "memory")
#define TCGEN05_WAIT_ST()  asm volatile("tcgen05.wait::st.sync.aligned;" ::: "memory")
#define TCGEN05_FENCE_BEFORE() asm volatile("tcgen05.fence::before_thread_sync;" ::: "memory")
#define TCGEN05_FENCE_AFTER()  asm volatile("tcgen05.fence::after_thread_sync;" ::: "memory")
#define FENCE_ASYNC() asm volatile("fence.proxy.async.shared::cta;" ::: "memory")

#define MBARRIER_WAIT_PARITY(mbar_smem_addr, phase_parity) do { \
    uint32_t _mbar = (uint32_t)(mbar_smem_addr); \
    uint32_t _par = (uint32_t)(phase_parity); \
    uint32_t _done; \
    asm volatile("{\n\t.reg .pred p;\n\t" \
        "mbarrier.try_wait.parity.acquire.cta.shared::cta.b64 p, [%1], %2;\n\t" \
        "selp.b32 %0, 1, 0, p;\n\t}" : "=r"(_done) : "r"(_mbar), "r"(_par) : "memory"); \
    if (!_done) { \
        asm volatile("{\n\t.reg .pred P1;\n\t" \
            "WAIT_LOOP_%=:\n\t" \
            "mbarrier.try_wait.parity.acquire.cta.shared::cta.b64 P1, [%0], %1, 0x989680;\n\t" \
            "@P1 bra.uni WAIT_DONE_%=;\n\tbra.uni WAIT_LOOP_%=;\n\tWAIT_DONE_%=:\n\t}" \
            :: "r"(_mbar), "r"(_par) : "memory"); \
    } \
} while (0)

#define TCGEN05_LD_X32(r, a) \
    asm volatile("tcgen05.ld.sync.aligned.32x32b.x32.b32 " \
        "{%0, %1, %2, %3, %4, %5, %6, %7, %8, %9, %10, %11, %12, %13, %14, %15, " \
        " %16, %17, %18, %19, %20, %21, %22, %23, %24, %25, %26, %27, %28, %29, %30, %31}, [%32];" \
        : "=r"((r)[0]),  "=r"((r)[1]),  "=r"((r)[2]),  "=r"((r)[3]), \
          "=r"((r)[4]),  "=r"((r)[5]),  "=r"((r)[6]),  "=r"((r)[7]), \
          "=r"((r)[8]),  "=r"((r)[9]),  "=r"((r)[10]), "=r"((r)[11]), \
          "=r"((r)[12]), "=r"((r)[13]), "=r"((r)[14]), "=r"((r)[15]), \
          "=r"((r)[16]), "=r"((r)[17]), "=r"((r)[18]), "=r"((r)[19]), \
          "=r"((r)[20]), "=r"((r)[21]), "=r"((r)[22]), "=r"((r)[23]), \
          "=r"((r)[24]), "=r"((r)[25]), "=r"((r)[26]), "=r"((r)[27]), \
          "=r"((r)[28]), "=r"((r)[29]), "=r"((r)[30]), "=r"((r)[31]) \
        : "r"(a))

#define TCGEN05_LD_X16(r, a) \
    asm volatile("tcgen05.ld.sync.aligned.32x32b.x16.b32 " \
        "{%0, %1, %2, %3, %4, %5, %6, %7, %8, %9, %10, %11, %12, %13, %14, %15}, [%16];" \
        : "=r"((r)[0]),  "=r"((r)[1]),  "=r"((r)[2]),  "=r"((r)[3]), \
          "=r"((r)[4]),  "=r"((r)[5]),  "=r"((r)[6]),  "=r"((r)[7]), \
          "=r"((r)[8]),  "=r"((r)[9]),  "=r"((r)[10]), "=r"((r)[11]), \
          "=r"((r)[12]), "=r"((r)[13]), "=r"((r)[14]), "=r"((r)[15]) \
        : "r"(a))

#define TCGEN05_ST_X16(a, r) \
    asm volatile("tcgen05.st.sync.aligned.32x32b.x16.b32 [%0], " \
        "{%1, %2, %3, %4, %5, %6, %7, %8, %9, %10, %11, %12, %13, %14, %15, %16};" \
        :: "r"(a), \
           "r"((r)[0]),  "r"((r)[1]),  "r"((r)[2]),  "r"((r)[3]), \
           "r"((r)[4]),  "r"((r)[5]),  "r"((r)[6]),  "r"((r)[7]), \
           "r"((r)[8]),  "r"((r)[9]),  "r"((r)[10]), "r"((r)[11]), \
           "r"((r)[12]), "r"((r)[13]), "r"((r)[14]), "r"((r)[15]) \
        : "memory")

#define TCGEN05_ST_X8(a, r) \
    asm volatile("tcgen05.st.sync.aligned.32x32b.x8.b32 [%0], " \
        "{%1, %2, %3, %4, %5, %6, %7, %8};" \
        :: "r"(a), \
           "r"((r)[0]), "r"((r)[1]), "r"((r)[2]), "r"((r)[3]), \
           "r"((r)[4]), "r"((r)[5]), "r"((r)[6]), "r"((r)[7]) \
        : "memory")

// idesc kind::f16: dtype=F32, a=FP16, b=FP16 (atype/btype=0), M=128 (cg1)
#define IDESC_F16_N128 ((1u << 4) | (16u << 17) | (8u << 24))
#define IDESC_F16_N64  ((1u << 4) | (8u << 17)  | (8u << 24))

__device__ __forceinline__ void mma_f16_ss(uint32_t d, uint64_t a, uint64_t b, uint32_t en) {
    asm volatile("{\n\t.reg .pred p;\n\tsetp.ne.u32 p, %4, 0;\n\t"
        "tcgen05.mma.cta_group::1.kind::f16 [%0], %1, %2, %3, {%5, %5, %5, %5}, p;\n\t}"
        :: "r"(d), "l"(a), "l"(b), "r"(IDESC_F16_N128), "r"(en), "r"(0u) : "memory");
}
__device__ __forceinline__ void mma_f16_ts_n64(uint32_t d, uint32_t a, uint64_t b, uint32_t en) {
    asm volatile("{\n\t.reg .pred p;\n\tsetp.ne.u32 p, %4, 0;\n\t"
        "tcgen05.mma.cta_group::1.kind::f16 [%0], [%1], %2, %3, {%5, %5, %5, %5}, p;\n\t}"
        :: "r"(d), "r"(a), "l"(b), "r"(IDESC_F16_N64), "r"(en), "r"(0u) : "memory");
}
#endif  // HAS_TCGEN05

// fallback rank-1 update macros (f32x2)
#define FMMA8x2(ACC, XA, XB, WP0, WP1)                                       \
    do { u64 _xx;                                                            \
        _xx = pack2f((XA).x, (XA).x); ACC[0][0]=fma2(_xx,WP0,ACC[0][0]); ACC[0][1]=fma2(_xx,WP1,ACC[0][1]); \
        _xx = pack2f((XA).y, (XA).y); ACC[1][0]=fma2(_xx,WP0,ACC[1][0]); ACC[1][1]=fma2(_xx,WP1,ACC[1][1]); \
        _xx = pack2f((XA).z, (XA).z); ACC[2][0]=fma2(_xx,WP0,ACC[2][0]); ACC[2][1]=fma2(_xx,WP1,ACC[2][1]); \
        _xx = pack2f((XA).w, (XA).w); ACC[3][0]=fma2(_xx,WP0,ACC[3][0]); ACC[3][1]=fma2(_xx,WP1,ACC[3][1]); \
        _xx = pack2f((XB).x, (XB).x); ACC[4][0]=fma2(_xx,WP0,ACC[4][0]); ACC[4][1]=fma2(_xx,WP1,ACC[4][1]); \
        _xx = pack2f((XB).y, (XB).y); ACC[5][0]=fma2(_xx,WP0,ACC[5][0]); ACC[5][1]=fma2(_xx,WP1,ACC[5][1]); \
        _xx = pack2f((XB).z, (XB).z); ACC[6][0]=fma2(_xx,WP0,ACC[6][0]); ACC[6][1]=fma2(_xx,WP1,ACC[6][1]); \
        _xx = pack2f((XB).w, (XB).w); ACC[7][0]=fma2(_xx,WP0,ACC[7][0]); ACC[7][1]=fma2(_xx,WP1,ACC[7][1]); \
    } while (0)

#define FMMA8x1(ACC, XA, XB, WP)                                             \
    do { u64 _xx;                                                            \
        _xx = pack2f((XA).x, (XA).x); ACC[0]=fma2(_xx,WP,ACC[0]);            \
        _xx = pack2f((XA).y, (XA).y); ACC[1]=fma2(_xx,WP,ACC[1]);            \
        _xx = pack2f((XA).z, (XA).z); ACC[2]=fma2(_xx,WP,ACC[2]);            \
        _xx = pack2f((XA).w, (XA).w); ACC[3]=fma2(_xx,WP,ACC[3]);            \
        _xx = pack2f((XB).x, (XB).x); ACC[4]=fma2(_xx,WP,ACC[4]);            \
        _xx = pack2f((XB).y, (XB).y); ACC[5]=fma2(_xx,WP,ACC[5]);            \
        _xx = pack2f((XB).z, (XB).z); ACC[6]=fma2(_xx,WP,ACC[6]);            \
        _xx = pack2f((XB).w, (XB).w); ACC[7]=fma2(_xx,WP,ACC[7]);            \
    } while (0)

// ==================== prep: swizzled fp16 weight images + b1eff ====================
__global__ void prep_kernel(const float* __restrict__ W1, const float* __restrict__ b1,
                            const float* __restrict__ W2, const float* __restrict__ ts)
{
    int idx = blockIdx.x * blockDim.x + threadIdx.x;
    if (idx < 65536) {                       // W1T[n=hidden j][k=dim]
        int j = idx >> 7, k = idx & 127;
        float w = W1[(size_t)k * HID + j];
        int c = j >> 7, n = j & 127;
        int sw = img_off(n, k);
        *(__half*)(g_w1img + c * 32768 + sw) = __float2half_rn(w);
    } else if (idx < 131072) {               // W2T[n=out dim][k=hidden]
        int t = idx - 65536;
        int kg = t >> 7, n = t & 127;
        float w = W2[(size_t)kg * DIMX + n];
        int c = kg >> 7, k = kg & 127;
        int sw = img_off(n, k);
        *(__half*)(g_w2img + c * 32768 + sw) = __float2half_rn(w);
    } else if (idx < 131072 + NSTEPS_ * HID) {
        int t = idx - 131072;
        int s = t >> 9, j = t & 511;
        g_b1eff[t] = b1[j] + ts[s] * W1[(size_t)DIMX * HID + j];
    }
}

// ==================== init: traj[0], ts tail ====================
__global__ void init_kernel(const float* __restrict__ y0, const float* __restrict__ ts,
                            float* __restrict__ out, int write_ts)
{
    size_t i = (size_t)blockIdx.x * blockDim.x + threadIdx.x;
    size_t r = i / OUTC;
    int c = (int)(i - r * OUTC);
    out[i] = (c < DIMX) ? y0[r * DIMX + c] : 0.0f;
    if (write_ts && i <= (size_t)NSTEPS_)
        out[(size_t)(NSTEPS_ + 1) * BATCH_ * OUTC + i] = ts[i];
}

// ==================== persistent kernel: all 20 steps ====================
__global__ __launch_bounds__(NTHREADS, 1)
void main_kernel(float* __restrict__ out, const float* __restrict__ y0g,
                 const float* __restrict__ noises,
                 const float* __restrict__ W1, const float* __restrict__ b1,
                 const float* __restrict__ W2, const float* __restrict__ b2,
                 const float* __restrict__ ts)
{
#if HAS_TCGEN05
    extern __shared__ unsigned char sm[];
    uint32_t smem_base = smem_to_u32(sm);
    const int tid  = threadIdx.x;
    const int lane = tid & 31;
    const int wid  = tid >> 5;
    const int sub  = wid & 3;          // subpartition
    const int cg   = wid >> 2;         // column group (0..3)
    const int row  = sub * 32 + lane;  // 0..127 within tile
    const int c0   = cg * 32;
    const int tile = blockIdx.x;
    const uint32_t st_warp_off = (uint32_t)sub << 21;
    float* b1e_s = (float*)(sm + B1EFF_OFF);
    float* b2_s  = (float*)(sm + B2S_OFF);
    // this warp's G1 half-barrier (cg 0/1 -> first N-half, cg 2/3 -> second)
    const uint32_t my_g1_bar = smem_base + ((cg < 2) ? MBAR1A_OFF : MBAR1B_OFF);

    if (tid == 0) {
        MBARRIER_INIT(smem_base + MBAR1A_OFF, 1);
        MBARRIER_INIT(smem_base + MBAR1B_OFF, 1);
        MBARRIER_INIT(smem_base + MBAR2_OFF, 1);
        MBARRIER_INIT(smem_base + MBW2_OFF, 1);
        MBARRIER_INIT(smem_base + MBW1_OFF, 1);
    }
    if (wid == 0) TCGEN05_ALLOC(smem_base + TPTR_OFF, 512);
    __syncthreads();
    uint32_t tmem_base;
    asm volatile("ld.shared.b32 %0, [%1];" : "=r"(tmem_base) : "r"(smem_base + TPTR_OFF));

    const uint64_t aHhi = MAKE_SMEM_DESC(smem_base + H_OFF);
    const uint64_t aHlo = MAKE_SMEM_DESC(smem_base + H_OFF + 32768);
    const uint64_t bW1e = MAKE_SMEM_DESC(smem_base + W1_OFF);       // slot0 (chunks 0,2)
    const uint64_t bW1o = MAKE_SMEM_DESC(smem_base + OUTBUF_OFF);   // slot1 (chunks 1,3)
    const uint64_t bW2  = MAKE_SMEM_DESC(smem_base + W2_OFF);
    const uint32_t w1slot_addr[2] = { smem_base + W1_OFF, smem_base + OUTBUF_OFF };

    // ---- startup: y0 -> X fp16 hi/lo + Y fp32 into TMEM; stage b2; W1(0) copy ----
    if (tid == 0) {
        MBARRIER_EXPECT_TX(smem_base + MBW1_OFF, 32768);
        BULK_COPY_G2S(smem_base + W1_OFF, g_w1img, 32768, smem_base + MBW1_OFF);
    }
    if (tid < DIMX) b2_s[tid] = b2[tid];
    {
        size_t grow = (size_t)tile * 128 + row;
        const float* yp = y0g + grow * DIMX + c0;
        uint32_t hv[16], lv[16], yv[32];
#pragma unroll
        for (int i = 0; i < 16; i++) {
            float a = yp[2 * i], b = yp[2 * i + 1];
            fp16_split2(a, b, hv[i], lv[i]);
            yv[2 * i] = __float_as_uint(a);
            yv[2 * i + 1] = __float_as_uint(b);
        }
        TCGEN05_ST_X16(tmem_base + T_XHI + cg * 16 + st_warp_off, hv);
        TCGEN05_ST_X16(tmem_base + T_XLO + cg * 16 + st_warp_off, lv);
        TCGEN05_ST_X16(tmem_base + T_Y + c0 + st_warp_off, yv);
        TCGEN05_ST_X16(tmem_base + T_Y + c0 + 16 + st_warp_off, yv + 16);
        TCGEN05_WAIT_ST();
        TCGEN05_FENCE_BEFORE();
    }
    __syncthreads();

    int p1 = 0, p2 = 0, pw2 = 0, pw1 = 0;
    int g2_pending = 0;
    float aug01 = 0.0f, aug2 = 0.0f;   // running aug state (cg0 threads own rows)

    for (int s = 0; s < NSTEPS_; s++) {
        const float dt = ts[s + 1] - ts[s];
        const float sq = sqrtf(dt);
        float*       next  = out + (size_t)(s + 1) * BATCH_ * OUTC;
        const float* noise = noises + (size_t)s * BATCH_ * DIMX;

        // stage this step's b1eff (made visible by chunk-0's __syncthreads)
        b1e_s[tid] = g_b1eff[s * HID + tid];

        for (int c = 0; c < 4; c++) {
            if (c == 0) __syncthreads();   // b1e_s visibility; OUTBUF/NOISE drained

            // non-issue warps: G2(c-1) completion gates H-epi's H overwrite
            if (g2_pending && wid != 0) MBARRIER_WAIT_PARITY(smem_base + MBAR2_OFF, p2);

            // ---- W1(c) copy ready? (only the MMA-issuing warp needs ordering) ----
            if (wid == 0) MBARRIER_WAIT_PARITY(smem_base + MBW1_OFF, pw1);
            pw1 ^= 1;

            // ---- issue GEMM1 split into two N=64 halves (TS: A = X in TMEM) ----
            const uint64_t bW1 = (c & 1) ? bW1o : bW1e;
            if (wid == 0) {
                if (elect_one_pred()) {
                    TCGEN05_FENCE_AFTER();
#pragma unroll
                    for (int g = 0; g < 8; g++) {
                        uint32_t off  = (g & 3) * 2 + (g >> 2) * 1024;
                        uint32_t acol = g * 8;
                        mma_f16_ts_n64(tmem_base + T_D1, tmem_base + T_XHI + acol, bW1 + off, g > 0);
                        mma_f16_ts_n64(tmem_base + T_D1, tmem_base + T_XLO + acol, bW1 + off, 1u);
                    }
                    TCGEN05_COMMIT(smem_base + MBAR1A_OFF);
#pragma unroll
                    for (int g = 0; g < 8; g++) {
                        uint32_t off  = (g & 3) * 2 + (g >> 2) * 1024 + 512;  // +8192 B: rows 64-127
                        uint32_t acol = g * 8;
                        mma_f16_ts_n64(tmem_base + T_D1 + 64, tmem_base + T_XHI + acol, bW1 + off, g > 0);
                        mma_f16_ts_n64(tmem_base + T_D1 + 64, tmem_base + T_XLO + acol, bW1 + off, 1u);
                    }
                    TCGEN05_COMMIT(smem_base + MBAR1B_OFF);
                }
            }

            // ---- prefetch W1 for the next chunk (wraps to next step's chunk 0).
            //      Target slot was last read by G1(c-1), complete by chunk-c top.
            if (tid == 0 && !(s == NSTEPS_ - 1 && c == 3)) {
                int nc = (c < 3) ? c + 1 : 0;
                MBARRIER_EXPECT_TX(smem_base + MBW1_OFF, 32768);
                BULK_COPY_G2S(w1slot_addr[nc & 1], g_w1img + nc * 32768, 32768,
                              smem_base + MBW1_OFF);
            }

            // ---- warp0: wait GEMM2(c-1) (frees W2 buffer + H) ----
            if (g2_pending) {
                if (wid == 0) MBARRIER_WAIT_PARITY(smem_base + MBAR2_OFF, p2);
                p2 ^= 1; g2_pending = 0;
            }
            if (tid == 0) {
                MBARRIER_EXPECT_TX(smem_base + MBW2_OFF, 32768);
                BULK_COPY_G2S(smem_base + W2_OFF, g_w2img + c * 32768, 32768, smem_base + MBW2_OFF);
            }

            // ---- wait only THIS warp's G1 half; H-epi(a) overlaps G1b drain ----
            MBARRIER_WAIT_PARITY(my_g1_bar, p1); p1 ^= 1;
            TCGEN05_FENCE_AFTER();
            {
                uint32_t r32[32];
                TCGEN05_LD_X32(r32, tmem_base + T_D1 + c0);
                TCGEN05_WAIT_LD();
                const float* bptr = b1e_s + c * 128 + c0;
#pragma unroll
                for (int gi = 0; gi < 4; gi++) {
                    uint32_t hv[4], lv[4];
#pragma unroll
                    for (int p = 0; p < 4; p++) {
                        int i0 = gi * 8 + p * 2;
                        float h0 = fast_tanh(__uint_as_float(r32[i0])     + bptr[i0]);
                        float h1 = fast_tanh(__uint_as_float(r32[i0 + 1]) + bptr[i0 + 1]);
                        fp16_split2(h0, h1, hv[p], lv[p]);
                    }
                    int k = c0 + gi * 8;
                    int sw = img_off(row, k);
                    asm volatile("st.shared.v4.b32 [%0], {%1, %2, %3, %4};"
                        :: "r"(smem_base + H_OFF + sw), "r"(hv[0]), "r"(hv[1]), "r"(hv[2]), "r"(hv[3]) : "memory");
                    asm volatile("st.shared.v4.b32 [%0], {%1, %2, %3, %4};"
                        :: "r"(smem_base + H_OFF + 32768 + sw), "r"(lv[0]), "r"(lv[1]), "r"(lv[2]), "r"(lv[3]) : "memory");
                }
            }
            FENCE_ASYNC();
            __syncthreads();   // H visible; D1 fully consumed (both halves)

            // ---- W2(c) copy complete? (issuer only; others gated by sync) ----
            if (wid == 0) MBARRIER_WAIT_PARITY(smem_base + MBW2_OFF, pw2);
            pw2 ^= 1;

            // ---- issue GEMM2 (SS, N=128), accumulate U ----
            if (wid == 0) {
                if (elect_one_pred()) {
                    TCGEN05_FENCE_AFTER();
#pragma unroll
                    for (int g = 0; g < 8; g++) {
                        uint32_t off = (g & 3) * 2 + (g >> 2) * 1024;
                        uint32_t en0 = (c > 0) || (g > 0);
                        mma_f16_ss(tmem_base + T_U, aHhi + off, bW2 + off, en0);
                        mma_f16_ss(tmem_base + T_U, aHlo + off, bW2 + off, 1u);
                    }
                    TCGEN05_COMMIT(smem_base + MBAR2_OFF);
                }
            }
            g2_pending = 1;
        }

        // ================= step epilogue =================
        // prefetch noise (fully coalesced) while GEMM2(3) drains
        float4 npref[8];
        {
            const float4* nb4 = (const float4*)(noise + (size_t)tile * 128 * DIMX);
#pragma unroll
            for (int i = 0; i < 8; i++) npref[i] = nb4[tid + i * NTHREADS];
        }

        MBARRIER_WAIT_PARITY(smem_base + MBAR2_OFF, p2); p2 ^= 1; g2_pending = 0;
        TCGEN05_FENCE_AFTER();

        // stage noise into rotated pitch-128 tile over the H region (dead now).
        // Per-element NB_IDX (rotated column wraps within the row).
        {
            float* ns = (float*)(sm + NOISE_OFF);
#pragma unroll
            for (int i = 0; i < 8; i++) {
                int idx = tid + i * NTHREADS;
                int r = idx >> 5, cc = (idx & 31) * 4;
                ns[NB_IDX(r, cc)]     = npref[i].x;
                ns[NB_IDX(r, cc + 1)] = npref[i].y;
                ns[NB_IDX(r, cc + 2)] = npref[i].z;
                ns[NB_IDX(r, cc + 3)] = npref[i].w;
            }
        }
        __syncthreads();

        // SDE math in LDTM layout; results to OUTBUF (rotated) + TMEM.
        // OUTBUF region's W1-slot1 image (chunk 3) was fully read by G1(3).
        {
            const float* ns = (const float*)(sm + NOISE_OFF);
            float* ob = (float*)(sm + OUTBUF_OFF);
            float udw = 0.0f, en = 0.0f;
#pragma unroll
            for (int h = 0; h < 2; h++) {
                uint32_t uv[16], yv[16];
                TCGEN05_LD_X16(uv, tmem_base + T_U + c0 + h * 16);
                TCGEN05_LD_X16(yv, tmem_base + T_Y + c0 + h * 16);
                TCGEN05_WAIT_LD();
                uint32_t hv[8], lv[8];
#pragma unroll
                for (int i2 = 0; i2 < 8; i2++) {
                    float yn2[2];
#pragma unroll
                    for (int q = 0; q < 2; q++) {
                        int i = i2 * 2 + q;
                        int col = c0 + h * 16 + i;
                        float u  = __uint_as_float(uv[i]) + b2_s[col];
                        float y  = __uint_as_float(yv[i]);
                        float nz = ns[NB_IDX(row, col)];
                        float ynew = y + (u - y) * dt + sq * nz;
                        udw += u * nz;
                        en  += u * u;
                        ob[OB_IDX(row, col)] = ynew;
                        yv[i] = __float_as_uint(ynew);
                        yn2[q] = ynew;
                    }
                    fp16_split2(yn2[0], yn2[1], hv[i2], lv[i2]);
                }
                TCGEN05_ST_X16(tmem_base + T_Y + c0 + h * 16 + st_warp_off, yv);
                TCGEN05_ST_X8(tmem_base + T_XHI + cg * 16 + h * 8 + st_warp_off, hv);
                TCGEN05_ST_X8(tmem_base + T_XLO + cg * 16 + h * 8 + st_warp_off, lv);
            }
            TCGEN05_WAIT_ST();
            TCGEN05_FENCE_BEFORE();

            ((float*)(sm + PUDW_OFF))[row * 4 + cg] = udw;
            ((float*)(sm + PEN_OFF))[row * 4 + cg]  = en;
        }
        __syncthreads();

        // aug channels (cg0 threads own one row each; running state in regs)
        if (cg == 0) {
            const float* pu = (const float*)(sm + PUDW_OFF) + row * 4;
            const float* pe = (const float*)(sm + PEN_OFF) + row * 4;
            float udw = pu[0] + pu[1] + pu[2] + pu[3];
            float en  = pe[0] + pe[1] + pe[2] + pe[3];
            aug01 += udw * sq;
            aug2  += 0.5f * en * dt;
            float* oa = next + ((size_t)tile * 128 + row) * OUTC + DIMX;
            oa[0] = aug01;
            oa[1] = aug01;
            oa[2] = aug2;
        }

        // coalesced y writes from rotated OUTBUF
        {
            const float* ob = (const float*)(sm + OUTBUF_OFF);
            float* nb = next + (size_t)tile * 128 * OUTC;
#pragma unroll
            for (int i = 0; i < 32; i++) {
                int e = tid + i * NTHREADS;
                int r = e >> 7, cc = e & 127;
                nb[(size_t)r * OUTC + cc] = ob[OB_IDX(r, cc)];
            }
        }
        __syncthreads();   // OUTBUF drained before next step's chunk-1 W1 copy
    }

    if (tid == 0) {
        MBARRIER_INVAL(smem_base + MBAR1A_OFF);
        MBARRIER_INVAL(smem_base + MBAR1B_OFF);
        MBARRIER_INVAL(smem_base + MBAR2_OFF);
        MBARRIER_INVAL(smem_base + MBW2_OFF);
        MBARRIER_INVAL(smem_base + MBW1_OFF);
    }
    __syncthreads();
    if (wid == 0) TCGEN05_DEALLOC(tmem_base, 512);

#else  // ======================= SIMT f32x2 fallback =======================
    extern __shared__ float smf[];
    float* XT  = smf + F_XT;
    float* W1s = smf + F_W1;
    float* HT  = smf + F_HT;
    float* W2s = smf + F_W2;
    float* b1s = smf + F_B1;
    float* b2s = smf + F_B2;

    const int tid   = threadIdx.x;
    const int tx    = tid & 31;
    const int wid   = tid >> 5;
    const int rbase = wid * 8;
    const int row0  = blockIdx.x * 128;

    for (int i = tid; i < HID; i += NTHREADS)  b1s[i] = b1[i];
    for (int i = tid; i < DIMX; i += NTHREADS) b2s[i] = b2[i];

    for (int s = 0; s < NSTEPS_; s++) {
        const float* prev  = out + (size_t)s * BATCH_ * OUTC;
        float*       next  = out + (size_t)(s + 1) * BATCH_ * OUTC;
        const float* noise = noises + (size_t)s * BATCH_ * DIMX;
        const float tp = ts[s];
        const float dt = ts[s + 1] - tp;
        const float sq = sqrtf(dt);

        __syncthreads();
        for (int idx = tid; idx < 128 * DIMX; idx += NTHREADS) {
            int r = idx >> 7, c = idx & 127;
            XT[c * F_PITCH + r] = prev[(size_t)(row0 + r) * OUTC + c];
        }
        for (int r = tid; r < 128; r += NTHREADS) XT[DIMX * F_PITCH + r] = tp;
        __syncthreads();

        u64 Uacc[8][2];
        {
            u64 pr0 = pack2f(b2s[tx], b2s[tx + 32]);
            u64 pr1 = pack2f(b2s[tx + 64], b2s[tx + 96]);
#pragma unroll
            for (int j = 0; j < 8; j++) { Uacc[j][0] = pr0; Uacc[j][1] = pr1; }
        }

        for (int ch = 0; ch < 8; ch++) {
            if (ch) __syncthreads();
            for (int idx = tid; idx < 129 * 16; idx += NTHREADS) {
                int k = idx >> 4, c4 = idx & 15;
                ((float4*)W1s)[k * 16 + c4] =
                    *(const float4*)&W1[(size_t)k * HID + ch * 64 + c4 * 4];
            }
            for (int idx = tid; idx < 64 * 32; idx += NTHREADS) {
                ((float4*)W2s)[idx] =
                    *(const float4*)&W2[(size_t)(ch * 64) * DIMX + idx * 4];
            }
            __syncthreads();

            u64 Hacc[8];
#pragma unroll
            for (int j = 0; j < 8; j++) Hacc[j] = 0ull;

#pragma unroll 2
            for (int k = 0; k < 129; k++) {
                const float* xrow = XT + k * F_PITCH + rbase;
                float4 xa = *(const float4*)(xrow);
                float4 xb = *(const float4*)(xrow + 4);
                u64 wp = pack2f(W1s[k * 64 + tx], W1s[k * 64 + tx + 32]);
                FMMA8x1(Hacc, xa, xb, wp);
            }
            {
                float bA = b1s[ch * 64 + tx];
                float bB = b1s[ch * 64 + tx + 32];
#pragma unroll
                for (int j = 0; j < 8; j++) {
                    float2 h = unpack2f(Hacc[j]);
                    int r = rbase + j;
                    HT[(tx)      * F_PITCH + r] = tanhf(h.x + bA);
                    HT[(tx + 32) * F_PITCH + r] = tanhf(h.y + bB);
                }
            }
            __syncthreads();

#pragma unroll 2
            for (int k = 0; k < 64; k++) {
                const float* hrow = HT + k * F_PITCH + rbase;
                float4 ha = *(const float4*)(hrow);
                float4 hb = *(const float4*)(hrow + 4);
                const float* wrow = W2s + k * DIMX + tx;
                u64 wp0 = pack2f(wrow[0], wrow[32]);
                u64 wp1 = pack2f(wrow[64], wrow[96]);
                FMMA8x2(Uacc, ha, hb, wp0, wp1);
            }
        }

#pragma unroll
        for (int j = 0; j < 8; j++) {
            int r = rbase + j;
            size_t grow = (size_t)(row0 + r);
            float2 u0 = unpack2f(Uacc[j][0]);
            float2 u1 = unpack2f(Uacc[j][1]);

            float yA = XT[(tx)      * F_PITCH + r];
            float yB = XT[(tx + 32) * F_PITCH + r];
            float yC = XT[(tx + 64) * F_PITCH + r];
            float yD = XT[(tx + 96) * F_PITCH + r];

            const float* np = noise + grow * DIMX;
            float nA = np[tx], nB = np[tx + 32], nC = np[tx + 64], nD = np[tx + 96];

            float* op = next + grow * OUTC;
            op[tx]      = yA + (u0.x - yA) * dt + sq * nA;
            op[tx + 32] = yB + (u0.y - yB) * dt + sq * nB;
            op[tx + 64] = yC + (u1.x - yC) * dt + sq * nC;
            op[tx + 96] = yD + (u1.y - yD) * dt + sq * nD;

            float udw = u0.x * nA + u0.y * nB + u1.x * nC + u1.y * nD;
            float en  = u0.x * u0.x + u0.y * u0.y + u1.x * u1.x + u1.y * u1.y;
#pragma unroll
            for (int off = 16; off; off >>= 1) {
                udw += __shfl_xor_sync(0xffffffffu, udw, off);
                en  += __shfl_xor_sync(0xffffffffu, en, off);
            }
            if (tx == 0) {
                const float* pp = prev + grow * OUTC + DIMX;
                float incr = udw * sq;
                op[DIMX]     = pp[0] + incr;
                op[DIMX + 1] = pp[1] + incr;
                op[DIMX + 2] = pp[2] + 0.5f * en * dt;
            }
        }
    }
#endif
}

extern "C" void kernel_launch(void* const* d_in, const int* in_sizes, int n_in,
                              void* d_out, int out_size)
{
    const float* y0     = (const float*)d_in[0];
    const float* W1     = (const float*)d_in[1];
    const float* b1     = (const float*)d_in[2];
    const float* W2     = (const float*)d_in[3];
    const float* b2     = (const float*)d_in[4];
    const float* noises = (const float*)d_in[5];
    const float* ts     = (const float*)d_in[6];
    float* out = (float*)d_out;

    cudaFuncSetAttribute(main_kernel,
                         cudaFuncAttributeMaxDynamicSharedMemorySize, SMEM_BYTES);

    size_t traj_elems = (size_t)(NSTEPS_ + 1) * BATCH_ * OUTC;
    int write_ts = ((size_t)out_size >= traj_elems + (NSTEPS_ + 1)) ? 1 : 0;

    prep_kernel<<<(131072 + NSTEPS_ * HID + 511) / 512, 512>>>(W1, b1, W2, ts);
    init_kernel<<<(BATCH_ * OUTC) / 512, 512>>>(y0, ts, out, write_ts);
    main_kernel<<<NTILES, NTHREADS, SMEM_BYTES>>>(out, y0, noises, W1, b1, W2, b2, ts);
}

// round 16
// speedup vs baseline: 1.4805x; 1.4805x over previous
#include <cuda_runtime.h>
#include <cuda_bf16.h>
#include <cuda_fp16.h>
#include <cstdint>
#include <math.h>

#define DIMX     128
#define HID      512
#define NSTEPS_  20
#define BATCH_   16384
#define OUTC     131
#define NTHREADS 512
#define NTILES   (BATCH_ / 128)      // 128 CTAs, one M=128 tile each

// ---- arch-specific feature gate (tcgen05 needs sm_10xa target) ----
#if defined(__CUDA_ARCH__)
#  if defined(__CUDA_ARCH_FEAT_SM103_ALL) || defined(__CUDA_ARCH_FEAT_SM100_ALL) || \
      (defined(__CUDA_ARCH_SPECIFIC__) && (__CUDA_ARCH_SPECIFIC__ == 1000 || \
       __CUDA_ARCH_SPECIFIC__ == 1010 || __CUDA_ARCH_SPECIFIC__ == 1030))
#    define HAS_TCGEN05 1
#  else
#    define HAS_TCGEN05 0
#  endif
#else
#  define HAS_TCGEN05 0
#endif

// ---- smem layout for tcgen05 path (bytes) ----
// fp16 is 2 B/elem: a [128][128] blocked-atom image is 32768 B.
#define MBAR1A_OFF 0
#define MBAR2_OFF  8
#define TPTR_OFF   16
#define MBW2_OFF   24
#define MBW1_OFF   32
#define MBAR1B_OFF 40
#define PUDW_OFF   1024              // 512 floats [1024,3072)
#define PEN_OFF    3072              // 512 floats [3072,5120)
#define B1EFF_OFF  5120              // 512 floats [5120,7168)
#define B2S_OFF    7168              // 128 floats [7168,7680)
#define H_OFF      8192              // Hhi 32KB, Hlo +32768  -> [8192,73728)
#define W1_OFF     73728             // fp16 single image 32KB -> [73728,106496)
#define W2_OFF     106496            // fp16 single image 32KB -> [106496,139264)
#define OUTBUF_OFF 139264            // 128x128 fp32 rotated 64KB -> [139264,204800)
#define SMEM_BYTES 204800
// epilogue NOISE overlays the H region EXACTLY: [8192,73728) = 65536 B,
// pitch 128 + odd rotation, per-element NB_IDX on both sides (the rotated
// column wraps within the row, so vectorized stores are illegal here).
// H is dead when staged (G2(3) completed); W1/W2 untouched by noise.
#define NOISE_OFF  H_OFF
#define NB_IDX(r, c) ((r) * 128 + (((c) + 5 * (r)) & 127))
#define OB_IDX(r, c) ((r) * 128 + (((c) + 5 * (r)) & 127))

// TMEM column offsets (512 total)
#define T_XHI  0
#define T_XLO  64
#define T_D1   128
#define T_U    256
#define T_Y    384

// ---- smem layout for SIMT fallback (floats) ----
#define F_XT    0                    // [129][132]
#define F_W1    17028                // [129][64]
#define F_HT    25284                // [64][132]
#define F_W2    33732                // [64][128]
#define F_B1    41924                // 512
#define F_B2    42436                // 128
#define F_PITCH 132

// ---- device scratch (no allocs allowed) ----
__device__ __align__(128) unsigned char g_w1img[4 * 32768];   // fp16 per chunk
__device__ __align__(128) unsigned char g_w2img[4 * 32768];   // fp16 per chunk
__device__ float g_b1eff[NSTEPS_ * HID];

// =========================== common helpers ===========================
__device__ __forceinline__ uint32_t smem_to_u32(const void* p) {
    uint32_t a;
    asm("{ .reg .u64 t; cvta.to.shared.u64 t, %1; cvt.u32.u64 %0, t; }" : "=r"(a) : "l"(p));
    return a;
}
#define SMEM_SWIZZLE_128B(b) ((b) ^ (((b) >> 3) & 0x70))

// blocked-atom SW128 image byte offset for [row][k] in a [128][128] fp16 tile
__device__ __forceinline__ int img_off(int row, int k) {
    int byte = ((row >> 3) + (k >> 6) * 16) * 1024 + (row & 7) * 128 + (k & 63) * 2;
    return SMEM_SWIZZLE_128B(byte);
}

typedef unsigned long long u64;
__device__ __forceinline__ u64 pack2f(float lo, float hi) {
    u64 r; asm("mov.b64 %0, {%1, %2};" : "=l"(r) : "f"(lo), "f"(hi)); return r;
}
__device__ __forceinline__ u64 fma2(u64 a, u64 b, u64 c) {
    u64 d; asm("fma.rn.f32x2 %0, %1, %2, %3;" : "=l"(d) : "l"(a), "l"(b), "l"(c)); return d;
}
__device__ __forceinline__ float2 unpack2f(u64 v) {
    float2 f; asm("mov.b64 {%0, %1}, %2;" : "=f"(f.x), "=f"(f.y) : "l"(v)); return f;
}

// fast tanh: tanh(x) = 1 - 2/(exp(2x)+1); MUFU ex2 + MUFU rcp, exact saturation
__device__ __forceinline__ float fast_tanh(float x) {
    float e, r;
    asm("ex2.approx.ftz.f32 %0, %1;" : "=f"(e) : "f"(x * 2.8853900817779268f));
    asm("rcp.approx.ftz.f32 %0, %1;" : "=f"(r) : "f"(e + 1.0f));
    return fmaf(-2.0f, r, 1.0f);
}

// fp16 hi/lo split of two floats -> packed half2 words
__device__ __forceinline__ void fp16_split2(float a, float b, uint32_t& hi, uint32_t& lo) {
    __half2 hp = __floats2half2_rn(a, b);
    float ra = a - __half2float(__low2half(hp));
    float rb = b - __half2float(__high2half(hp));
    __half2 lp = __floats2half2_rn(ra, rb);
    hi = *(uint32_t*)&hp;
    lo = *(uint32_t*)&lp;
}

#if HAS_TCGEN05
// =========================== tcgen05 helpers ===========================
__device__ __forceinline__ uint32_t elect_one_pred() {
    uint32_t pred;
    asm volatile("{\n\t.reg .pred p;\n\telect.sync _|p, 0xFFFFFFFF;\n\t"
                 "selp.b32 %0, 1, 0, p;\n\t}" : "=r"(pred));
    return pred;
}
static constexpr uint64_t SMEM_DESC_BASE_SW128 =
    (uint64_t(2) << 61) | (uint64_t(1) << 46) | (uint64_t(64) << 32) | (uint64_t(1) << 16);
#define MAKE_SMEM_DESC(addr) (SMEM_DESC_BASE_SW128 | ((uint64_t)((addr) >> 4) & 0x3FFF))

#define MBARRIER_INIT(a, n) \
    asm volatile("mbarrier.init.shared.b64 [%0], %1;" :: "r"((uint32_t)(a)), "r"((uint32_t)(n)) : "memory")
#define MBARRIER_INVAL(a) \
    asm volatile("mbarrier.inval.shared.b64 [%0];" :: "r"((uint32_t)(a)) : "memory")
#define MBARRIER_EXPECT_TX(a, bytes) \
    asm volatile("mbarrier.arrive.expect_tx.shared.b64 _, [%0], %1;" \
                 :: "r"((uint32_t)(a)), "r"((uint32_t)(bytes)) : "memory")
#define BULK_COPY_G2S(dst, src, bytes, mbar) \
    asm volatile("cp.async.bulk.shared::cta.global.mbarrier::complete_tx::bytes [%0], [%1], %2, [%3];" \
                 :: "r"((uint32_t)(dst)), "l"(src), "r"((uint32_t)(bytes)), "r"((uint32_t)(mbar)) : "memory")
#define TCGEN05_ALLOC(sa, n) \
    asm volatile("tcgen05.alloc.cta_group::1.sync.aligned.shared::cta.b32 [%0], %1;" \
                 :: "r"((uint32_t)(sa)), "r"((uint32_t)(n)) : "memory")
#define TCGEN05_DEALLOC(t, n) \
    asm volatile("tcgen05.dealloc.cta_group::1.sync.aligned.b32 %0, %1;" :: "r"(t), "r"((uint32_t)(n)))
#define TCGEN05_COMMIT(a) \
    asm volatile("tcgen05.commit.cta_group::1.mbarrier::arrive::one.shared::cluster.b64 [%0];" \
                 :: "r"((uint32_t)(a)) : "memory")
#define TCGEN05_WAIT_LD()  asm volatile("tcgen05.wait::ld.sync.aligned;" ::: "memory")
#define TCGEN05_WAIT_ST()  asm volatile("tcgen05.wait::st.sync.aligned;" ::: "memory")
#define TCGEN05_FENCE_BEFORE() asm volatile("tcgen05.fence::before_thread_sync;" ::: "memory")
#define TCGEN05_FENCE_AFTER()  asm volatile("tcgen05.fence::after_thread_sync;" ::: "memory")
#define FENCE_ASYNC() asm volatile("fence.proxy.async.shared::cta;" ::: "memory")

#define MBARRIER_WAIT_PARITY(mbar_smem_addr, phase_parity) do { \
    uint32_t _mbar = (uint32_t)(mbar_smem_addr); \
    uint32_t _par = (uint32_t)(phase_parity); \
    uint32_t _done; \
    asm volatile("{\n\t.reg .pred p;\n\t" \
        "mbarrier.try_wait.parity.acquire.cta.shared::cta.b64 p, [%1], %2;\n\t" \
        "selp.b32 %0, 1, 0, p;\n\t}" : "=r"(_done) : "r"(_mbar), "r"(_par) : "memory"); \
    if (!_done) { \
        asm volatile("{\n\t.reg .pred P1;\n\t" \
            "WAIT_LOOP_%=:\n\t" \
            "mbarrier.try_wait.parity.acquire.cta.shared::cta.b64 P1, [%0], %1, 0x989680;\n\t" \
            "@P1 bra.uni WAIT_DONE_%=;\n\tbra.uni WAIT_LOOP_%=;\n\tWAIT_DONE_%=:\n\t}" \
            :: "r"(_mbar), "r"(_par) : "memory"); \
    } \
} while (0)

#define TCGEN05_LD_X32(r, a) \
    asm volatile("tcgen05.ld.sync.aligned.32x32b.x32.b32 " \
        "{%0, %1, %2, %3, %4, %5, %6, %7, %8, %9, %10, %11, %12, %13, %14, %15, " \
        " %16, %17, %18, %19, %20, %21, %22, %23, %24, %25, %26, %27, %28, %29, %30, %31}, [%32];" \
        : "=r"((r)[0]),  "=r"((r)[1]),  "=r"((r)[2]),  "=r"((r)[3]), \
          "=r"((r)[4]),  "=r"((r)[5]),  "=r"((r)[6]),  "=r"((r)[7]), \
          "=r"((r)[8]),  "=r"((r)[9]),  "=r"((r)[10]), "=r"((r)[11]), \
          "=r"((r)[12]), "=r"((r)[13]), "=r"((r)[14]), "=r"((r)[15]), \
          "=r"((r)[16]), "=r"((r)[17]), "=r"((r)[18]), "=r"((r)[19]), \
          "=r"((r)[20]), "=r"((r)[21]), "=r"((r)[22]), "=r"((r)[23]), \
          "=r"((r)[24]), "=r"((r)[25]), "=r"((r)[26]), "=r"((r)[27]), \
          "=r"((r)[28]), "=r"((r)[29]), "=r"((r)[30]), "=r"((r)[31]) \
        : "r"(a))

#define TCGEN05_LD_X16(r, a) \
    asm volatile("tcgen05.ld.sync.aligned.32x32b.x16.b32 " \
        "{%0, %1, %2, %3, %4, %5, %6, %7, %8, %9, %10, %11, %12, %13, %14, %15}, [%16];" \
        : "=r"((r)[0]),  "=r"((r)[1]),  "=r"((r)[2]),  "=r"((r)[3]), \
          "=r"((r)[4]),  "=r"((r)[5]),  "=r"((r)[6]),  "=r"((r)[7]), \
          "=r"((r)[8]),  "=r"((r)[9]),  "=r"((r)[10]), "=r"((r)[11]), \
          "=r"((r)[12]), "=r"((r)[13]), "=r"((r)[14]), "=r"((r)[15]) \
        : "r"(a))

#define TCGEN05_ST_X16(a, r) \
    asm volatile("tcgen05.st.sync.aligned.32x32b.x16.b32 [%0], " \
        "{%1, %2, %3, %4, %5, %6, %7, %8, %9, %10, %11, %12, %13, %14, %15, %16};" \
        :: "r"(a), \
           "r"((r)[0]),  "r"((r)[1]),  "r"((r)[2]),  "r"((r)[3]), \
           "r"((r)[4]),  "r"((r)[5]),  "r"((r)[6]),  "r"((r)[7]), \
           "r"((r)[8]),  "r"((r)[9]),  "r"((r)[10]), "r"((r)[11]), \
           "r"((r)[12]), "r"((r)[13]), "r"((r)[14]), "r"((r)[15]) \
        : "memory")

#define TCGEN05_ST_X8(a, r) \
    asm volatile("tcgen05.st.sync.aligned.32x32b.x8.b32 [%0], " \
        "{%1, %2, %3, %4, %5, %6, %7, %8};" \
        :: "r"(a), \
           "r"((r)[0]), "r"((r)[1]), "r"((r)[2]), "r"((r)[3]), \
           "r"((r)[4]), "r"((r)[5]), "r"((r)[6]), "r"((r)[7]) \
        : "memory")

// idesc kind::f16: dtype=F32, a=FP16, b=FP16 (atype/btype=0), M=128 (cg1)
#define IDESC_F16_N128 ((1u << 4) | (16u << 17) | (8u << 24))
#define IDESC_F16_N64  ((1u << 4) | (8u << 17)  | (8u << 24))

__device__ __forceinline__ void mma_f16_ss(uint32_t d, uint64_t a, uint64_t b, uint32_t en) {
    asm volatile("{\n\t.reg .pred p;\n\tsetp.ne.u32 p, %4, 0;\n\t"
        "tcgen05.mma.cta_group::1.kind::f16 [%0], %1, %2, %3, {%5, %5, %5, %5}, p;\n\t}"
        :: "r"(d), "l"(a), "l"(b), "r"(IDESC_F16_N128), "r"(en), "r"(0u) : "memory");
}
__device__ __forceinline__ void mma_f16_ts_n64(uint32_t d, uint32_t a, uint64_t b, uint32_t en) {
    asm volatile("{\n\t.reg .pred p;\n\tsetp.ne.u32 p, %4, 0;\n\t"
        "tcgen05.mma.cta_group::1.kind::f16 [%0], [%1], %2, %3, {%5, %5, %5, %5}, p;\n\t}"
        :: "r"(d), "r"(a), "l"(b), "r"(IDESC_F16_N64), "r"(en), "r"(0u) : "memory");
}
#endif  // HAS_TCGEN05

// fallback rank-1 update macros (f32x2)
#define FMMA8x2(ACC, XA, XB, WP0, WP1)                                       \
    do { u64 _xx;                                                            \
        _xx = pack2f((XA).x, (XA).x); ACC[0][0]=fma2(_xx,WP0,ACC[0][0]); ACC[0][1]=fma2(_xx,WP1,ACC[0][1]); \
        _xx = pack2f((XA).y, (XA).y); ACC[1][0]=fma2(_xx,WP0,ACC[1][0]); ACC[1][1]=fma2(_xx,WP1,ACC[1][1]); \
        _xx = pack2f((XA).z, (XA).z); ACC[2][0]=fma2(_xx,WP0,ACC[2][0]); ACC[2][1]=fma2(_xx,WP1,ACC[2][1]); \
        _xx = pack2f((XA).w, (XA).w); ACC[3][0]=fma2(_xx,WP0,ACC[3][0]); ACC[3][1]=fma2(_xx,WP1,ACC[3][1]); \
        _xx = pack2f((XB).x, (XB).x); ACC[4][0]=fma2(_xx,WP0,ACC[4][0]); ACC[4][1]=fma2(_xx,WP1,ACC[4][1]); \
        _xx = pack2f((XB).y, (XB).y); ACC[5][0]=fma2(_xx,WP0,ACC[5][0]); ACC[5][1]=fma2(_xx,WP1,ACC[5][1]); \
        _xx = pack2f((XB).z, (XB).z); ACC[6][0]=fma2(_xx,WP0,ACC[6][0]); ACC[6][1]=fma2(_xx,WP1,ACC[6][1]); \
        _xx = pack2f((XB).w, (XB).w); ACC[7][0]=fma2(_xx,WP0,ACC[7][0]); ACC[7][1]=fma2(_xx,WP1,ACC[7][1]); \
    } while (0)

#define FMMA8x1(ACC, XA, XB, WP)                                             \
    do { u64 _xx;                                                            \
        _xx = pack2f((XA).x, (XA).x); ACC[0]=fma2(_xx,WP,ACC[0]);            \
        _xx = pack2f((XA).y, (XA).y); ACC[1]=fma2(_xx,WP,ACC[1]);            \
        _xx = pack2f((XA).z, (XA).z); ACC[2]=fma2(_xx,WP,ACC[2]);            \
        _xx = pack2f((XA).w, (XA).w); ACC[3]=fma2(_xx,WP,ACC[3]);            \
        _xx = pack2f((XB).x, (XB).x); ACC[4]=fma2(_xx,WP,ACC[4]);            \
        _xx = pack2f((XB).y, (XB).y); ACC[5]=fma2(_xx,WP,ACC[5]);            \
        _xx = pack2f((XB).z, (XB).z); ACC[6]=fma2(_xx,WP,ACC[6]);            \
        _xx = pack2f((XB).w, (XB).w); ACC[7]=fma2(_xx,WP,ACC[7]);            \
    } while (0)

// ==================== prep: swizzled fp16 weight images + b1eff ====================
__global__ void prep_kernel(const float* __restrict__ W1, const float* __restrict__ b1,
                            const float* __restrict__ W2, const float* __restrict__ ts)
{
    int idx = blockIdx.x * blockDim.x + threadIdx.x;
    if (idx < 65536) {                       // W1T[n=hidden j][k=dim]
        int j = idx >> 7, k = idx & 127;
        float w = W1[(size_t)k * HID + j];
        int c = j >> 7, n = j & 127;
        int sw = img_off(n, k);
        *(__half*)(g_w1img + c * 32768 + sw) = __float2half_rn(w);
    } else if (idx < 131072) {               // W2T[n=out dim][k=hidden]
        int t = idx - 65536;
        int kg = t >> 7, n = t & 127;
        float w = W2[(size_t)kg * DIMX + n];
        int c = kg >> 7, k = kg & 127;
        int sw = img_off(n, k);
        *(__half*)(g_w2img + c * 32768 + sw) = __float2half_rn(w);
    } else if (idx < 131072 + NSTEPS_ * HID) {
        int t = idx - 131072;
        int s = t >> 9, j = t & 511;
        g_b1eff[t] = b1[j] + ts[s] * W1[(size_t)DIMX * HID + j];
    }
}

// ==================== init: traj[0], ts tail ====================
__global__ void init_kernel(const float* __restrict__ y0, const float* __restrict__ ts,
                            float* __restrict__ out, int write_ts)
{
    size_t i = (size_t)blockIdx.x * blockDim.x + threadIdx.x;
    size_t r = i / OUTC;
    int c = (int)(i - r * OUTC);
    out[i] = (c < DIMX) ? y0[r * DIMX + c] : 0.0f;
    if (write_ts && i <= (size_t)NSTEPS_)
        out[(size_t)(NSTEPS_ + 1) * BATCH_ * OUTC + i] = ts[i];
}

// ==================== persistent kernel: all 20 steps ====================
__global__ __launch_bounds__(NTHREADS, 1)
void main_kernel(float* __restrict__ out, const float* __restrict__ y0g,
                 const float* __restrict__ noises,
                 const float* __restrict__ W1, const float* __restrict__ b1,
                 const float* __restrict__ W2, const float* __restrict__ b2,
                 const float* __restrict__ ts)
{
#if HAS_TCGEN05
    extern __shared__ unsigned char sm[];
    uint32_t smem_base = smem_to_u32(sm);
    const int tid  = threadIdx.x;
    const int lane = tid & 31;
    const int wid  = tid >> 5;
    const int sub  = wid & 3;          // subpartition
    const int cg   = wid >> 2;         // column group (0..3)
    const int row  = sub * 32 + lane;  // 0..127 within tile
    const int c0   = cg * 32;
    const int tile = blockIdx.x;
    const uint32_t st_warp_off = (uint32_t)sub << 21;
    float* b1e_s = (float*)(sm + B1EFF_OFF);
    float* b2_s  = (float*)(sm + B2S_OFF);
    // this warp's G1 half-barrier (cg 0/1 -> first N-half, cg 2/3 -> second)
    const uint32_t my_g1_bar = smem_base + ((cg < 2) ? MBAR1A_OFF : MBAR1B_OFF);

    if (tid == 0) {
        MBARRIER_INIT(smem_base + MBAR1A_OFF, 1);
        MBARRIER_INIT(smem_base + MBAR1B_OFF, 1);
        MBARRIER_INIT(smem_base + MBAR2_OFF, 1);
        MBARRIER_INIT(smem_base + MBW2_OFF, 1);
        MBARRIER_INIT(smem_base + MBW1_OFF, 1);
    }
    if (wid == 0) TCGEN05_ALLOC(smem_base + TPTR_OFF, 512);
    __syncthreads();
    uint32_t tmem_base;
    asm volatile("ld.shared.b32 %0, [%1];" : "=r"(tmem_base) : "r"(smem_base + TPTR_OFF));

    const uint64_t aHhi = MAKE_SMEM_DESC(smem_base + H_OFF);
    const uint64_t aHlo = MAKE_SMEM_DESC(smem_base + H_OFF + 32768);
    const uint64_t bW1  = MAKE_SMEM_DESC(smem_base + W1_OFF);
    const uint64_t bW2  = MAKE_SMEM_DESC(smem_base + W2_OFF);

    // ---- startup: y0 -> X fp16 hi/lo + Y fp32 into TMEM; stage b2; W1(0) copy ----
    if (tid == 0) {
        MBARRIER_EXPECT_TX(smem_base + MBW1_OFF, 32768);
        BULK_COPY_G2S(smem_base + W1_OFF, g_w1img, 32768, smem_base + MBW1_OFF);
    }
    if (tid < DIMX) b2_s[tid] = b2[tid];
    {
        size_t grow = (size_t)tile * 128 + row;
        const float* yp = y0g + grow * DIMX + c0;
        uint32_t hv[16], lv[16], yv[32];
#pragma unroll
        for (int i = 0; i < 16; i++) {
            float a = yp[2 * i], b = yp[2 * i + 1];
            fp16_split2(a, b, hv[i], lv[i]);
            yv[2 * i] = __float_as_uint(a);
            yv[2 * i + 1] = __float_as_uint(b);
        }
        TCGEN05_ST_X16(tmem_base + T_XHI + cg * 16 + st_warp_off, hv);
        TCGEN05_ST_X16(tmem_base + T_XLO + cg * 16 + st_warp_off, lv);
        TCGEN05_ST_X16(tmem_base + T_Y + c0 + st_warp_off, yv);
        TCGEN05_ST_X16(tmem_base + T_Y + c0 + 16 + st_warp_off, yv + 16);
        TCGEN05_WAIT_ST();
        TCGEN05_FENCE_BEFORE();
    }
    __syncthreads();

    int p1 = 0, p2 = 0, pw2 = 0, pw1 = 0;
    int g2_pending = 0;
    float aug01 = 0.0f, aug2 = 0.0f;   // running aug state (cg0 threads own rows)

    for (int s = 0; s < NSTEPS_; s++) {
        const float dt = ts[s + 1] - ts[s];
        const float sq = sqrtf(dt);
        float*       next  = out + (size_t)(s + 1) * BATCH_ * OUTC;
        const float* noise = noises + (size_t)s * BATCH_ * DIMX;

        // stage this step's b1eff (made visible by chunk-0's __syncthreads)
        b1e_s[tid] = g_b1eff[s * HID + tid];

        for (int c = 0; c < 4; c++) {
            if (c == 0) {
                // W1(0) was TMA-copied during the previous step's epilogue
                MBARRIER_WAIT_PARITY(smem_base + MBW1_OFF, pw1); pw1 ^= 1;
                __syncthreads();   // b1e_s visibility + align warps
            } else {
                // stage W1 chunk (register path — overlaps G2(c-1) drain)
                const uint4* src = (const uint4*)(g_w1img + c * 32768);
                uint4* dst = (uint4*)(sm + W1_OFF);
#pragma unroll
                for (int i = 0; i < 4; i++) dst[tid + i * NTHREADS] = src[tid + i * NTHREADS];
                FENCE_ASYNC();
                __syncthreads();
            }

            // ---- issue GEMM1 split into two N=64 halves (TS: A = X in TMEM) ----
            if (wid == 0) {
                if (elect_one_pred()) {
                    TCGEN05_FENCE_AFTER();
#pragma unroll
                    for (int g = 0; g < 8; g++) {
                        uint32_t off  = (g & 3) * 2 + (g >> 2) * 1024;
                        uint32_t acol = g * 8;
                        mma_f16_ts_n64(tmem_base + T_D1, tmem_base + T_XHI + acol, bW1 + off, g > 0);
                        mma_f16_ts_n64(tmem_base + T_D1, tmem_base + T_XLO + acol, bW1 + off, 1u);
                    }
                    TCGEN05_COMMIT(smem_base + MBAR1A_OFF);
#pragma unroll
                    for (int g = 0; g < 8; g++) {
                        uint32_t off  = (g & 3) * 2 + (g >> 2) * 1024 + 512;  // +8192 B: rows 64-127
                        uint32_t acol = g * 8;
                        mma_f16_ts_n64(tmem_base + T_D1 + 64, tmem_base + T_XHI + acol, bW1 + off, g > 0);
                        mma_f16_ts_n64(tmem_base + T_D1 + 64, tmem_base + T_XLO + acol, bW1 + off, 1u);
                    }
                    TCGEN05_COMMIT(smem_base + MBAR1B_OFF);
                }
            }

            // ---- wait GEMM2(c-1) (frees W2 buffer), then async-copy W2(c) ----
            if (g2_pending) { MBARRIER_WAIT_PARITY(smem_base + MBAR2_OFF, p2); p2 ^= 1; g2_pending = 0; }
            if (tid == 0) {
                MBARRIER_EXPECT_TX(smem_base + MBW2_OFF, 32768);
                BULK_COPY_G2S(smem_base + W2_OFF, g_w2img + c * 32768, 32768, smem_base + MBW2_OFF);
            }

            // ---- wait only THIS warp's G1 half; H-epi(a) overlaps G1b drain ----
            MBARRIER_WAIT_PARITY(my_g1_bar, p1); p1 ^= 1;
            TCGEN05_FENCE_AFTER();
            {
                uint32_t r32[32];
                TCGEN05_LD_X32(r32, tmem_base + T_D1 + c0);
                TCGEN05_WAIT_LD();
                const float* bptr = b1e_s + c * 128 + c0;
#pragma unroll
                for (int gi = 0; gi < 4; gi++) {
                    uint32_t hv[4], lv[4];
#pragma unroll
                    for (int p = 0; p < 4; p++) {
                        int i0 = gi * 8 + p * 2;
                        float h0 = fast_tanh(__uint_as_float(r32[i0])     + bptr[i0]);
                        float h1 = fast_tanh(__uint_as_float(r32[i0 + 1]) + bptr[i0 + 1]);
                        fp16_split2(h0, h1, hv[p], lv[p]);
                    }
                    int k = c0 + gi * 8;
                    int sw = img_off(row, k);
                    asm volatile("st.shared.v4.b32 [%0], {%1, %2, %3, %4};"
                        :: "r"(smem_base + H_OFF + sw), "r"(hv[0]), "r"(hv[1]), "r"(hv[2]), "r"(hv[3]) : "memory");
                    asm volatile("st.shared.v4.b32 [%0], {%1, %2, %3, %4};"
                        :: "r"(smem_base + H_OFF + 32768 + sw), "r"(lv[0]), "r"(lv[1]), "r"(lv[2]), "r"(lv[3]) : "memory");
                }
            }
            FENCE_ASYNC();
            __syncthreads();   // H visible; D1 fully consumed (both halves)

            // ---- W2(c) copy complete? (overlapped G1 drain + H-epi) ----
            MBARRIER_WAIT_PARITY(smem_base + MBW2_OFF, pw2); pw2 ^= 1;

            // ---- issue GEMM2 (SS, N=128), accumulate U ----
            if (wid == 0) {
                if (elect_one_pred()) {
                    TCGEN05_FENCE_AFTER();
#pragma unroll
                    for (int g = 0; g < 8; g++) {
                        uint32_t off = (g & 3) * 2 + (g >> 2) * 1024;
                        uint32_t en0 = (c > 0) || (g > 0);
                        mma_f16_ss(tmem_base + T_U, aHhi + off, bW2 + off, en0);
                        mma_f16_ss(tmem_base + T_U, aHlo + off, bW2 + off, 1u);
                    }
                    TCGEN05_COMMIT(smem_base + MBAR2_OFF);
                }
            }
            g2_pending = 1;
        }

        // ================= step epilogue =================
        // prefetch noise (fully coalesced) while GEMM2(3) drains
        float4 npref[8];
        {
            const float4* nb4 = (const float4*)(noise + (size_t)tile * 128 * DIMX);
#pragma unroll
            for (int i = 0; i < 8; i++) npref[i] = nb4[tid + i * NTHREADS];
        }

        MBARRIER_WAIT_PARITY(smem_base + MBAR2_OFF, p2); p2 ^= 1; g2_pending = 0;
        TCGEN05_FENCE_AFTER();

        // stage noise into rotated pitch-128 tile over the H region (dead now).
        // Per-element NB_IDX (rotated column wraps within the row).
        {
            float* ns = (float*)(sm + NOISE_OFF);
#pragma unroll
            for (int i = 0; i < 8; i++) {
                int idx = tid + i * NTHREADS;
                int r = idx >> 5, cc = (idx & 31) * 4;
                ns[NB_IDX(r, cc)]     = npref[i].x;
                ns[NB_IDX(r, cc + 1)] = npref[i].y;
                ns[NB_IDX(r, cc + 2)] = npref[i].z;
                ns[NB_IDX(r, cc + 3)] = npref[i].w;
            }
        }
        __syncthreads();

        // SDE math in LDTM layout; results to OUTBUF (dedicated, rotated) + TMEM
        {
            const float* ns = (const float*)(sm + NOISE_OFF);
            float* ob = (float*)(sm + OUTBUF_OFF);
            float udw = 0.0f, en = 0.0f;
#pragma unroll
            for (int h = 0; h < 2; h++) {
                uint32_t uv[16], yv[16];
                TCGEN05_LD_X16(uv, tmem_base + T_U + c0 + h * 16);
                TCGEN05_LD_X16(yv, tmem_base + T_Y + c0 + h * 16);
                TCGEN05_WAIT_LD();
                uint32_t hv[8], lv[8];
#pragma unroll
                for (int i2 = 0; i2 < 8; i2++) {
                    float yn2[2];
#pragma unroll
                    for (int q = 0; q < 2; q++) {
                        int i = i2 * 2 + q;
                        int col = c0 + h * 16 + i;
                        float u  = __uint_as_float(uv[i]) + b2_s[col];
                        float y  = __uint_as_float(yv[i]);
                        float nz = ns[NB_IDX(row, col)];
                        float ynew = y + (u - y) * dt + sq * nz;
                        udw += u * nz;
                        en  += u * u;
                        ob[OB_IDX(row, col)] = ynew;
                        yv[i] = __float_as_uint(ynew);
                        yn2[q] = ynew;
                    }
                    fp16_split2(yn2[0], yn2[1], hv[i2], lv[i2]);
                }
                TCGEN05_ST_X16(tmem_base + T_Y + c0 + h * 16 + st_warp_off, yv);
                TCGEN05_ST_X8(tmem_base + T_XHI + cg * 16 + h * 8 + st_warp_off, hv);
                TCGEN05_ST_X8(tmem_base + T_XLO + cg * 16 + h * 8 + st_warp_off, lv);
            }
            TCGEN05_WAIT_ST();
            TCGEN05_FENCE_BEFORE();

            ((float*)(sm + PUDW_OFF))[row * 4 + cg] = udw;
            ((float*)(sm + PEN_OFF))[row * 4 + cg]  = en;
        }
        __syncthreads();

        // kick next step's W1(0) copy — overlaps aug + y write-out below.
        // Safe: noise fully consumed; W1 region untouched by noise anyway.
        if (s < NSTEPS_ - 1 && tid == 0) {
            MBARRIER_EXPECT_TX(smem_base + MBW1_OFF, 32768);
            BULK_COPY_G2S(smem_base + W1_OFF, g_w1img, 32768, smem_base + MBW1_OFF);
        }

        // aug channels (cg0 threads own one row each; running state in regs)
        if (cg == 0) {
            const float* pu = (const float*)(sm + PUDW_OFF) + row * 4;
            const float* pe = (const float*)(sm + PEN_OFF) + row * 4;
            float udw = pu[0] + pu[1] + pu[2] + pu[3];
            float en  = pe[0] + pe[1] + pe[2] + pe[3];
            aug01 += udw * sq;
            aug2  += 0.5f * en * dt;
            float* oa = next + ((size_t)tile * 128 + row) * OUTC + DIMX;
            oa[0] = aug01;
            oa[1] = aug01;
            oa[2] = aug2;
        }

        // coalesced y writes from rotated OUTBUF
        {
            const float* ob = (const float*)(sm + OUTBUF_OFF);
            float* nb = next + (size_t)tile * 128 * OUTC;
#pragma unroll
            for (int i = 0; i < 32; i++) {
                int e = tid + i * NTHREADS;
                int r = e >> 7, cc = e & 127;
                nb[(size_t)r * OUTC + cc] = ob[OB_IDX(r, cc)];
            }
        }
        __syncthreads();   // scratch regions reused next step
    }

    if (tid == 0) {
        MBARRIER_INVAL(smem_base + MBAR1A_OFF);
        MBARRIER_INVAL(smem_base + MBAR1B_OFF);
        MBARRIER_INVAL(smem_base + MBAR2_OFF);
        MBARRIER_INVAL(smem_base + MBW2_OFF);
        MBARRIER_INVAL(smem_base + MBW1_OFF);
    }
    __syncthreads();
    if (wid == 0) TCGEN05_DEALLOC(tmem_base, 512);

#else  // ======================= SIMT f32x2 fallback =======================
    extern __shared__ float smf[];
    float* XT  = smf + F_XT;
    float* W1s = smf + F_W1;
    float* HT  = smf + F_HT;
    float* W2s = smf + F_W2;
    float* b1s = smf + F_B1;
    float* b2s = smf + F_B2;

    const int tid   = threadIdx.x;
    const int tx    = tid & 31;
    const int wid   = tid >> 5;
    const int rbase = wid * 8;
    const int row0  = blockIdx.x * 128;

    for (int i = tid; i < HID; i += NTHREADS)  b1s[i] = b1[i];
    for (int i = tid; i < DIMX; i += NTHREADS) b2s[i] = b2[i];

    for (int s = 0; s < NSTEPS_; s++) {
        const float* prev  = out + (size_t)s * BATCH_ * OUTC;
        float*       next  = out + (size_t)(s + 1) * BATCH_ * OUTC;
        const float* noise = noises + (size_t)s * BATCH_ * DIMX;
        const float tp = ts[s];
        const float dt = ts[s + 1] - tp;
        const float sq = sqrtf(dt);

        __syncthreads();
        for (int idx = tid; idx < 128 * DIMX; idx += NTHREADS) {
            int r = idx >> 7, c = idx & 127;
            XT[c * F_PITCH + r] = prev[(size_t)(row0 + r) * OUTC + c];
        }
        for (int r = tid; r < 128; r += NTHREADS) XT[DIMX * F_PITCH + r] = tp;
        __syncthreads();

        u64 Uacc[8][2];
        {
            u64 pr0 = pack2f(b2s[tx], b2s[tx + 32]);
            u64 pr1 = pack2f(b2s[tx + 64], b2s[tx + 96]);
#pragma unroll
            for (int j = 0; j < 8; j++) { Uacc[j][0] = pr0; Uacc[j][1] = pr1; }
        }

        for (int ch = 0; ch < 8; ch++) {
            if (ch) __syncthreads();
            for (int idx = tid; idx < 129 * 16; idx += NTHREADS) {
                int k = idx >> 4, c4 = idx & 15;
                ((float4*)W1s)[k * 16 + c4] =
                    *(const float4*)&W1[(size_t)k * HID + ch * 64 + c4 * 4];
            }
            for (int idx = tid; idx < 64 * 32; idx += NTHREADS) {
                ((float4*)W2s)[idx] =
                    *(const float4*)&W2[(size_t)(ch * 64) * DIMX + idx * 4];
            }
            __syncthreads();

            u64 Hacc[8];
#pragma unroll
            for (int j = 0; j < 8; j++) Hacc[j] = 0ull;

#pragma unroll 2
            for (int k = 0; k < 129; k++) {
                const float* xrow = XT + k * F_PITCH + rbase;
                float4 xa = *(const float4*)(xrow);
                float4 xb = *(const float4*)(xrow + 4);
                u64 wp = pack2f(W1s[k * 64 + tx], W1s[k * 64 + tx + 32]);
                FMMA8x1(Hacc, xa, xb, wp);
            }
            {
                float bA = b1s[ch * 64 + tx];
                float bB = b1s[ch * 64 + tx + 32];
#pragma unroll
                for (int j = 0; j < 8; j++) {
                    float2 h = unpack2f(Hacc[j]);
                    int r = rbase + j;
                    HT[(tx)      * F_PITCH + r] = tanhf(h.x + bA);
                    HT[(tx + 32) * F_PITCH + r] = tanhf(h.y + bB);
                }
            }
            __syncthreads();

#pragma unroll 2
            for (int k = 0; k < 64; k++) {
                const float* hrow = HT + k * F_PITCH + rbase;
                float4 ha = *(const float4*)(hrow);
                float4 hb = *(const float4*)(hrow + 4);
                const float* wrow = W2s + k * DIMX + tx;
                u64 wp0 = pack2f(wrow[0], wrow[32]);
                u64 wp1 = pack2f(wrow[64], wrow[96]);
                FMMA8x2(Uacc, ha, hb, wp0, wp1);
            }
        }

#pragma unroll
        for (int j = 0; j < 8; j++) {
            int r = rbase + j;
            size_t grow = (size_t)(row0 + r);
            float2 u0 = unpack2f(Uacc[j][0]);
            float2 u1 = unpack2f(Uacc[j][1]);

            float yA = XT[(tx)      * F_PITCH + r];
            float yB = XT[(tx + 32) * F_PITCH + r];
            float yC = XT[(tx + 64) * F_PITCH + r];
            float yD = XT[(tx + 96) * F_PITCH + r];

            const float* np = noise + grow * DIMX;
            float nA = np[tx], nB = np[tx + 32], nC = np[tx + 64], nD = np[tx + 96];

            float* op = next + grow * OUTC;
            op[tx]      = yA + (u0.x - yA) * dt + sq * nA;
            op[tx + 32] = yB + (u0.y - yB) * dt + sq * nB;
            op[tx + 64] = yC + (u1.x - yC) * dt + sq * nC;
            op[tx + 96] = yD + (u1.y - yD) * dt + sq * nD;

            float udw = u0.x * nA + u0.y * nB + u1.x * nC + u1.y * nD;
            float en  = u0.x * u0.x + u0.y * u0.y + u1.x * u1.x + u1.y * u1.y;
#pragma unroll
            for (int off = 16; off; off >>= 1) {
                udw += __shfl_xor_sync(0xffffffffu, udw, off);
                en  += __shfl_xor_sync(0xffffffffu, en, off);
            }
            if (tx == 0) {
                const float* pp = prev + grow * OUTC + DIMX;
                float incr = udw * sq;
                op[DIMX]     = pp[0] + incr;
                op[DIMX + 1] = pp[1] + incr;
                op[DIMX + 2] = pp[2] + 0.5f * en * dt;
            }
        }
    }
#endif
}

extern "C" void kernel_launch(void* const* d_in, const int* in_sizes, int n_in,
                              void* d_out, int out_size)
{
    const float* y0     = (const float*)d_in[0];
    const float* W1     = (const float*)d_in[1];
    const float* b1     = (const float*)d_in[2];
    const float* W2     = (const float*)d_in[3];
    const float* b2     = (const float*)d_in[4];
    const float* noises = (const float*)d_in[5];
    const float* ts     = (const float*)d_in[6];
    float* out = (float*)d_out;

    cudaFuncSetAttribute(main_kernel,
                         cudaFuncAttributeMaxDynamicSharedMemorySize, SMEM_BYTES);

    size_t traj_elems = (size_t)(NSTEPS_ + 1) * BATCH_ * OUTC;
    int write_ts = ((size_t)out_size >= traj_elems + (NSTEPS_ + 1)) ? 1 : 0;

    prep_kernel<<<(131072 + NSTEPS_ * HID + 511) / 512, 512>>>(W1, b1, W2, ts);
    init_kernel<<<(BATCH_ * OUTC) / 512, 512>>>(y0, ts, out, write_ts);
    main_kernel<<<NTILES, NTHREADS, SMEM_BYTES>>>(out, y0, noises, W1, b1, W2, b2, ts);
}

// round 17
// speedup vs baseline: 1.7110x; 1.1557x over previous
#include <cuda_runtime.h>
#include <cuda_bf16.h>
#include <cuda_fp16.h>
#include <cstdint>
#include <math.h>

#define DIMX     128
#define HID      512
#define NSTEPS_  20
#define BATCH_   16384
#define OUTC     131
#define NTHREADS 512
#define NTILES   (BATCH_ / 128)      // 128 CTAs, one M=128 tile each

// ---- arch-specific feature gate (tcgen05 needs sm_10xa target) ----
#if defined(__CUDA_ARCH__)
#  if defined(__CUDA_ARCH_FEAT_SM103_ALL) || defined(__CUDA_ARCH_FEAT_SM100_ALL) || \
      (defined(__CUDA_ARCH_SPECIFIC__) && (__CUDA_ARCH_SPECIFIC__ == 1000 || \
       __CUDA_ARCH_SPECIFIC__ == 1010 || __CUDA_ARCH_SPECIFIC__ == 1030))
#    define HAS_TCGEN05 1
#  else
#    define HAS_TCGEN05 0
#  endif
#else
#  define HAS_TCGEN05 0
#endif

// ---- smem layout for tcgen05 path (bytes) ----
// fp16 is 2 B/elem: a [128][128] blocked-atom image is 32768 B.
// (Hlo region [H_OFF+32768, 73728) is now unused by GEMMs — kept reserved
// because the epilogue NOISE overlay spans it.)
#define MBAR1A_OFF 0
#define MBAR2_OFF  8
#define TPTR_OFF   16
#define MBW2_OFF   24
#define MBW1_OFF   32
#define MBAR1B_OFF 40
#define PUDW_OFF   1024              // 512 floats [1024,3072)
#define PEN_OFF    3072              // 512 floats [3072,5120)
#define B1EFF_OFF  5120              // 512 floats [5120,7168)
#define B2S_OFF    7168              // 128 floats [7168,7680)
#define H_OFF      8192              // Hhi 32KB -> [8192,40960); [40960,73728) spare
#define W1_OFF     73728             // fp16 single image 32KB -> [73728,106496)
#define W2_OFF     106496            // fp16 single image 32KB -> [106496,139264)
#define OUTBUF_OFF 139264            // 128x128 fp32 rotated 64KB -> [139264,204800)
#define SMEM_BYTES 204800
// epilogue NOISE overlays [8192,73728) = 65536 B (H tile + spare),
// pitch 128 + odd rotation, per-element NB_IDX on both sides.
#define NOISE_OFF  H_OFF
#define NB_IDX(r, c) ((r) * 128 + (((c) + 5 * (r)) & 127))
#define OB_IDX(r, c) ((r) * 128 + (((c) + 5 * (r)) & 127))

// TMEM column offsets (512 total; T_XLO retired)
#define T_XHI  0
#define T_D1   128
#define T_U    256
#define T_Y    384

// ---- smem layout for SIMT fallback (floats) ----
#define F_XT    0                    // [129][132]
#define F_W1    17028                // [129][64]
#define F_HT    25284                // [64][132]
#define F_W2    33732                // [64][128]
#define F_B1    41924                // 512
#define F_B2    42436                // 128
#define F_PITCH 132

// ---- device scratch (no allocs allowed) ----
__device__ __align__(128) unsigned char g_w1img[4 * 32768];   // fp16 per chunk
__device__ __align__(128) unsigned char g_w2img[4 * 32768];   // fp16 per chunk
__device__ float g_b1eff[NSTEPS_ * HID];

// =========================== common helpers ===========================
__device__ __forceinline__ uint32_t smem_to_u32(const void* p) {
    uint32_t a;
    asm("{ .reg .u64 t; cvta.to.shared.u64 t, %1; cvt.u32.u64 %0, t; }" : "=r"(a) : "l"(p));
    return a;
}
#define SMEM_SWIZZLE_128B(b) ((b) ^ (((b) >> 3) & 0x70))

// blocked-atom SW128 image byte offset for [row][k] in a [128][128] fp16 tile
__device__ __forceinline__ int img_off(int row, int k) {
    int byte = ((row >> 3) + (k >> 6) * 16) * 1024 + (row & 7) * 128 + (k & 63) * 2;
    return SMEM_SWIZZLE_128B(byte);
}

typedef unsigned long long u64;
__device__ __forceinline__ u64 pack2f(float lo, float hi) {
    u64 r; asm("mov.b64 %0, {%1, %2};" : "=l"(r) : "f"(lo), "f"(hi)); return r;
}
__device__ __forceinline__ u64 fma2(u64 a, u64 b, u64 c) {
    u64 d; asm("fma.rn.f32x2 %0, %1, %2, %3;" : "=l"(d) : "l"(a), "l"(b), "l"(c)); return d;
}
__device__ __forceinline__ float2 unpack2f(u64 v) {
    float2 f; asm("mov.b64 {%0, %1}, %2;" : "=f"(f.x), "=f"(f.y) : "l"(v)); return f;
}

// fast tanh: tanh(x) = 1 - 2/(exp(2x)+1); MUFU ex2 + MUFU rcp, exact saturation
__device__ __forceinline__ float fast_tanh(float x) {
    float e, r;
    asm("ex2.approx.ftz.f32 %0, %1;" : "=f"(e) : "f"(x * 2.8853900817779268f));
    asm("rcp.approx.ftz.f32 %0, %1;" : "=f"(r) : "f"(e + 1.0f));
    return fmaf(-2.0f, r, 1.0f);
}

// pack two floats into one fp16x2 word (round-to-nearest)
__device__ __forceinline__ uint32_t fp16_pack2(float a, float b) {
    __half2 hp = __floats2half2_rn(a, b);
    return *(uint32_t*)&hp;
}

#if HAS_TCGEN05
// =========================== tcgen05 helpers ===========================
__device__ __forceinline__ uint32_t elect_one_pred() {
    uint32_t pred;
    asm volatile("{\n\t.reg .pred p;\n\telect.sync _|p, 0xFFFFFFFF;\n\t"
                 "selp.b32 %0, 1, 0, p;\n\t}" : "=r"(pred));
    return pred;
}
static constexpr uint64_t SMEM_DESC_BASE_SW128 =
    (uint64_t(2) << 61) | (uint64_t(1) << 46) | (uint64_t(64) << 32) | (uint64_t(1) << 16);
#define MAKE_SMEM_DESC(addr) (SMEM_DESC_BASE_SW128 | ((uint64_t)((addr) >> 4) & 0x3FFF))

#define MBARRIER_INIT(a, n) \
    asm volatile("mbarrier.init.shared.b64 [%0], %1;" :: "r"((uint32_t)(a)), "r"((uint32_t)(n)) : "memory")
#define MBARRIER_INVAL(a) \
    asm volatile("mbarrier.inval.shared.b64 [%0];" :: "r"((uint32_t)(a)) : "memory")
#define MBARRIER_EXPECT_TX(a, bytes) \
    asm volatile("mbarrier.arrive.expect_tx.shared.b64 _, [%0], %1;" \
                 :: "r"((uint32_t)(a)), "r"((uint32_t)(bytes)) : "memory")
#define BULK_COPY_G2S(dst, src, bytes, mbar) \
    asm volatile("cp.async.bulk.shared::cta.global.mbarrier::complete_tx::bytes [%0], [%1], %2, [%3];" \
                 :: "r"((uint32_t)(dst)), "l"(src), "r"((uint32_t)(bytes)), "r"((uint32_t)(mbar)) : "memory")
#define TCGEN05_ALLOC(sa, n) \
    asm volatile("tcgen05.alloc.cta_group::1.sync.aligned.shared::cta.b32 [%0], %1;" \
                 :: "r"((uint32_t)(sa)), "r"((uint32_t)(n)) : "memory")
#define TCGEN05_DEALLOC(t, n) \
    asm volatile("tcgen05.dealloc.cta_group::1.sync.aligned.b32 %0, %1;" :: "r"(t), "r"((uint32_t)(n)))
#define TCGEN05_COMMIT(a) \
    asm volatile("tcgen05.commit.cta_group::1.mbarrier::arrive::one.shared::cluster.b64 [%0];" \
                 :: "r"((uint32_t)(a)) : "memory")
#define TCGEN05_WAIT_LD()  asm volatile("tcgen05.wait::ld.sync.aligned;" ::: "memory")
#define TCGEN05_WAIT_ST()  asm volatile("tcgen05.wait::st.sync.aligned;" ::: "memory")
#define TCGEN05_FENCE_BEFORE() asm volatile("tcgen05.fence::before_thread_sync;" ::: "memory")
#define TCGEN05_FENCE_AFTER()  asm volatile("tcgen05.fence::after_thread_sync;" ::: "memory")
#define FENCE_ASYNC() asm volatile("fence.proxy.async.shared::cta;" ::: "memory")

#define MBARRIER_WAIT_PARITY(mbar_smem_addr, phase_parity) do { \
    uint32_t _mbar = (uint32_t)(mbar_smem_addr); \
    uint32_t _par = (uint32_t)(phase_parity); \
    uint32_t _done; \
    asm volatile("{\n\t.reg .pred p;\n\t" \
        "mbarrier.try_wait.parity.acquire.cta.shared::cta.b64 p, [%1], %2;\n\t" \
        "selp.b32 %0, 1, 0, p;\n\t}" : "=r"(_done) : "r"(_mbar), "r"(_par) : "memory"); \
    if (!_done) { \
        asm volatile("{\n\t.reg .pred P1;\n\t" \
            "WAIT_LOOP_%=:\n\t" \
            "mbarrier.try_wait.parity.acquire.cta.shared::cta.b64 P1, [%0], %1, 0x989680;\n\t" \
            "@P1 bra.uni WAIT_DONE_%=;\n\tbra.uni WAIT_LOOP_%=;\n\tWAIT_DONE_%=:\n\t}" \
            :: "r"(_mbar), "r"(_par) : "memory"); \
    } \
} while (0)

#define TCGEN05_LD_X32(r, a) \
    asm volatile("tcgen05.ld.sync.aligned.32x32b.x32.b32 " \
        "{%0, %1, %2, %3, %4, %5, %6, %7, %8, %9, %10, %11, %12, %13, %14, %15, " \
        " %16, %17, %18, %19, %20, %21, %22, %23, %24, %25, %26, %27, %28, %29, %30, %31}, [%32];" \
        : "=r"((r)[0]),  "=r"((r)[1]),  "=r"((r)[2]),  "=r"((r)[3]), \
          "=r"((r)[4]),  "=r"((r)[5]),  "=r"((r)[6]),  "=r"((r)[7]), \
          "=r"((r)[8]),  "=r"((r)[9]),  "=r"((r)[10]), "=r"((r)[11]), \
          "=r"((r)[12]), "=r"((r)[13]), "=r"((r)[14]), "=r"((r)[15]), \
          "=r"((r)[16]), "=r"((r)[17]), "=r"((r)[18]), "=r"((r)[19]), \
          "=r"((r)[20]), "=r"((r)[21]), "=r"((r)[22]), "=r"((r)[23]), \
          "=r"((r)[24]), "=r"((r)[25]), "=r"((r)[26]), "=r"((r)[27]), \
          "=r"((r)[28]), "=r"((r)[29]), "=r"((r)[30]), "=r"((r)[31]) \
        : "r"(a))

#define TCGEN05_LD_X16(r, a) \
    asm volatile("tcgen05.ld.sync.aligned.32x32b.x16.b32 " \
        "{%0, %1, %2, %3, %4, %5, %6, %7, %8, %9, %10, %11, %12, %13, %14, %15}, [%16];" \
        : "=r"((r)[0]),  "=r"((r)[1]),  "=r"((r)[2]),  "=r"((r)[3]), \
          "=r"((r)[4]),  "=r"((r)[5]),  "=r"((r)[6]),  "=r"((r)[7]), \
          "=r"((r)[8]),  "=r"((r)[9]),  "=r"((r)[10]), "=r"((r)[11]), \
          "=r"((r)[12]), "=r"((r)[13]), "=r"((r)[14]), "=r"((r)[15]) \
        : "r"(a))

#define TCGEN05_ST_X16(a, r) \
    asm volatile("tcgen05.st.sync.aligned.32x32b.x16.b32 [%0], " \
        "{%1, %2, %3, %4, %5, %6, %7, %8, %9, %10, %11, %12, %13, %14, %15, %16};" \
        :: "r"(a), \
           "r"((r)[0]),  "r"((r)[1]),  "r"((r)[2]),  "r"((r)[3]), \
           "r"((r)[4]),  "r"((r)[5]),  "r"((r)[6]),  "r"((r)[7]), \
           "r"((r)[8]),  "r"((r)[9]),  "r"((r)[10]), "r"((r)[11]), \
           "r"((r)[12]), "r"((r)[13]), "r"((r)[14]), "r"((r)[15]) \
        : "memory")

#define TCGEN05_ST_X8(a, r) \
    asm volatile("tcgen05.st.sync.aligned.32x32b.x8.b32 [%0], " \
        "{%1, %2, %3, %4, %5, %6, %7, %8};" \
        :: "r"(a), \
           "r"((r)[0]), "r"((r)[1]), "r"((r)[2]), "r"((r)[3]), \
           "r"((r)[4]), "r"((r)[5]), "r"((r)[6]), "r"((r)[7]) \
        : "memory")

// idesc kind::f16: dtype=F32, a=FP16, b=FP16 (atype/btype=0), M=128 (cg1)
#define IDESC_F16_N128 ((1u << 4) | (16u << 17) | (8u << 24))
#define IDESC_F16_N64  ((1u << 4) | (8u << 17)  | (8u << 24))

__device__ __forceinline__ void mma_f16_ss(uint32_t d, uint64_t a, uint64_t b, uint32_t en) {
    asm volatile("{\n\t.reg .pred p;\n\tsetp.ne.u32 p, %4, 0;\n\t"
        "tcgen05.mma.cta_group::1.kind::f16 [%0], %1, %2, %3, {%5, %5, %5, %5}, p;\n\t}"
        :: "r"(d), "l"(a), "l"(b), "r"(IDESC_F16_N128), "r"(en), "r"(0u) : "memory");
}
__device__ __forceinline__ void mma_f16_ts_n64(uint32_t d, uint32_t a, uint64_t b, uint32_t en) {
    asm volatile("{\n\t.reg .pred p;\n\tsetp.ne.u32 p, %4, 0;\n\t"
        "tcgen05.mma.cta_group::1.kind::f16 [%0], [%1], %2, %3, {%5, %5, %5, %5}, p;\n\t}"
        :: "r"(d), "r"(a), "l"(b), "r"(IDESC_F16_N64), "r"(en), "r"(0u) : "memory");
}
#endif  // HAS_TCGEN05

// fallback rank-1 update macros (f32x2)
#define FMMA8x2(ACC, XA, XB, WP0, WP1)                                       \
    do { u64 _xx;                                                            \
        _xx = pack2f((XA).x, (XA).x); ACC[0][0]=fma2(_xx,WP0,ACC[0][0]); ACC[0][1]=fma2(_xx,WP1,ACC[0][1]); \
        _xx = pack2f((XA).y, (XA).y); ACC[1][0]=fma2(_xx,WP0,ACC[1][0]); ACC[1][1]=fma2(_xx,WP1,ACC[1][1]); \
        _xx = pack2f((XA).z, (XA).z); ACC[2][0]=fma2(_xx,WP0,ACC[2][0]); ACC[2][1]=fma2(_xx,WP1,ACC[2][1]); \
        _xx = pack2f((XA).w, (XA).w); ACC[3][0]=fma2(_xx,WP0,ACC[3][0]); ACC[3][1]=fma2(_xx,WP1,ACC[3][1]); \
        _xx = pack2f((XB).x, (XB).x); ACC[4][0]=fma2(_xx,WP0,ACC[4][0]); ACC[4][1]=fma2(_xx,WP1,ACC[4][1]); \
        _xx = pack2f((XB).y, (XB).y); ACC[5][0]=fma2(_xx,WP0,ACC[5][0]); ACC[5][1]=fma2(_xx,WP1,ACC[5][1]); \
        _xx = pack2f((XB).z, (XB).z); ACC[6][0]=fma2(_xx,WP0,ACC[6][0]); ACC[6][1]=fma2(_xx,WP1,ACC[6][1]); \
        _xx = pack2f((XB).w, (XB).w); ACC[7][0]=fma2(_xx,WP0,ACC[7][0]); ACC[7][1]=fma2(_xx,WP1,ACC[7][1]); \
    } while (0)

#define FMMA8x1(ACC, XA, XB, WP)                                             \
    do { u64 _xx;                                                            \
        _xx = pack2f((XA).x, (XA).x); ACC[0]=fma2(_xx,WP,ACC[0]);            \
        _xx = pack2f((XA).y, (XA).y); ACC[1]=fma2(_xx,WP,ACC[1]);            \
        _xx = pack2f((XA).z, (XA).z); ACC[2]=fma2(_xx,WP,ACC[2]);            \
        _xx = pack2f((XA).w, (XA).w); ACC[3]=fma2(_xx,WP,ACC[3]);            \
        _xx = pack2f((XB).x, (XB).x); ACC[4]=fma2(_xx,WP,ACC[4]);            \
        _xx = pack2f((XB).y, (XB).y); ACC[5]=fma2(_xx,WP,ACC[5]);            \
        _xx = pack2f((XB).z, (XB).z); ACC[6]=fma2(_xx,WP,ACC[6]);            \
        _xx = pack2f((XB).w, (XB).w); ACC[7]=fma2(_xx,WP,ACC[7]);            \
    } while (0)

// ==================== prep: swizzled fp16 weight images + b1eff ====================
__global__ void prep_kernel(const float* __restrict__ W1, const float* __restrict__ b1,
                            const float* __restrict__ W2, const float* __restrict__ ts)
{
    int idx = blockIdx.x * blockDim.x + threadIdx.x;
    if (idx < 65536) {                       // W1T[n=hidden j][k=dim]
        int j = idx >> 7, k = idx & 127;
        float w = W1[(size_t)k * HID + j];
        int c = j >> 7, n = j & 127;
        int sw = img_off(n, k);
        *(__half*)(g_w1img + c * 32768 + sw) = __float2half_rn(w);
    } else if (idx < 131072) {               // W2T[n=out dim][k=hidden]
        int t = idx - 65536;
        int kg = t >> 7, n = t & 127;
        float w = W2[(size_t)kg * DIMX + n];
        int c = kg >> 7, k = kg & 127;
        int sw = img_off(n, k);
        *(__half*)(g_w2img + c * 32768 + sw) = __float2half_rn(w);
    } else if (idx < 131072 + NSTEPS_ * HID) {
        int t = idx - 131072;
        int s = t >> 9, j = t & 511;
        g_b1eff[t] = b1[j] + ts[s] * W1[(size_t)DIMX * HID + j];
    }
}

// ==================== init: traj[0], ts tail ====================
__global__ void init_kernel(const float* __restrict__ y0, const float* __restrict__ ts,
                            float* __restrict__ out, int write_ts)
{
    size_t i = (size_t)blockIdx.x * blockDim.x + threadIdx.x;
    size_t r = i / OUTC;
    int c = (int)(i - r * OUTC);
    out[i] = (c < DIMX) ? y0[r * DIMX + c] : 0.0f;
    if (write_ts && i <= (size_t)NSTEPS_)
        out[(size_t)(NSTEPS_ + 1) * BATCH_ * OUTC + i] = ts[i];
}

// ==================== persistent kernel: all 20 steps ====================
__global__ __launch_bounds__(NTHREADS, 1)
void main_kernel(float* __restrict__ out, const float* __restrict__ y0g,
                 const float* __restrict__ noises,
                 const float* __restrict__ W1, const float* __restrict__ b1,
                 const float* __restrict__ W2, const float* __restrict__ b2,
                 const float* __restrict__ ts)
{
#if HAS_TCGEN05
    extern __shared__ unsigned char sm[];
    uint32_t smem_base = smem_to_u32(sm);
    const int tid  = threadIdx.x;
    const int lane = tid & 31;
    const int wid  = tid >> 5;
    const int sub  = wid & 3;          // subpartition
    const int cg   = wid >> 2;         // column group (0..3)
    const int row  = sub * 32 + lane;  // 0..127 within tile
    const int c0   = cg * 32;
    const int tile = blockIdx.x;
    const uint32_t st_warp_off = (uint32_t)sub << 21;
    float* b1e_s = (float*)(sm + B1EFF_OFF);
    float* b2_s  = (float*)(sm + B2S_OFF);
    // this warp's G1 half-barrier (cg 0/1 -> first N-half, cg 2/3 -> second)
    const uint32_t my_g1_bar = smem_base + ((cg < 2) ? MBAR1A_OFF : MBAR1B_OFF);

    if (tid == 0) {
        MBARRIER_INIT(smem_base + MBAR1A_OFF, 1);
        MBARRIER_INIT(smem_base + MBAR1B_OFF, 1);
        MBARRIER_INIT(smem_base + MBAR2_OFF, 1);
        MBARRIER_INIT(smem_base + MBW2_OFF, 1);
        MBARRIER_INIT(smem_base + MBW1_OFF, 1);
    }
    if (wid == 0) TCGEN05_ALLOC(smem_base + TPTR_OFF, 512);
    __syncthreads();
    uint32_t tmem_base;
    asm volatile("ld.shared.b32 %0, [%1];" : "=r"(tmem_base) : "r"(smem_base + TPTR_OFF));

    const uint64_t aHhi = MAKE_SMEM_DESC(smem_base + H_OFF);
    const uint64_t bW1  = MAKE_SMEM_DESC(smem_base + W1_OFF);
    const uint64_t bW2  = MAKE_SMEM_DESC(smem_base + W2_OFF);

    // ---- startup: y0 -> X fp16 + Y fp32 into TMEM; stage b2; W1(0) copy ----
    if (tid == 0) {
        MBARRIER_EXPECT_TX(smem_base + MBW1_OFF, 32768);
        BULK_COPY_G2S(smem_base + W1_OFF, g_w1img, 32768, smem_base + MBW1_OFF);
    }
    if (tid < DIMX) b2_s[tid] = b2[tid];
    {
        size_t grow = (size_t)tile * 128 + row;
        const float* yp = y0g + grow * DIMX + c0;
        uint32_t hv[16], yv[32];
#pragma unroll
        for (int i = 0; i < 16; i++) {
            float a = yp[2 * i], b = yp[2 * i + 1];
            hv[i] = fp16_pack2(a, b);
            yv[2 * i] = __float_as_uint(a);
            yv[2 * i + 1] = __float_as_uint(b);
        }
        TCGEN05_ST_X16(tmem_base + T_XHI + cg * 16 + st_warp_off, hv);
        TCGEN05_ST_X16(tmem_base + T_Y + c0 + st_warp_off, yv);
        TCGEN05_ST_X16(tmem_base + T_Y + c0 + 16 + st_warp_off, yv + 16);
        TCGEN05_WAIT_ST();
        TCGEN05_FENCE_BEFORE();
    }
    __syncthreads();

    int p1 = 0, p2 = 0, pw2 = 0, pw1 = 0;
    int g2_pending = 0;
    float aug01 = 0.0f, aug2 = 0.0f;   // running aug state (cg0 threads own rows)

    for (int s = 0; s < NSTEPS_; s++) {
        const float dt = ts[s + 1] - ts[s];
        const float sq = sqrtf(dt);
        float*       next  = out + (size_t)(s + 1) * BATCH_ * OUTC;
        const float* noise = noises + (size_t)s * BATCH_ * DIMX;

        // stage this step's b1eff (made visible by chunk-0's __syncthreads)
        b1e_s[tid] = g_b1eff[s * HID + tid];

        for (int c = 0; c < 4; c++) {
            if (c == 0) {
                // W1(0) was TMA-copied during the previous step's epilogue
                MBARRIER_WAIT_PARITY(smem_base + MBW1_OFF, pw1); pw1 ^= 1;
                __syncthreads();   // b1e_s visibility + align warps
            } else {
                // stage W1 chunk (register path — overlaps G2(c-1) drain)
                const uint4* src = (const uint4*)(g_w1img + c * 32768);
                uint4* dst = (uint4*)(sm + W1_OFF);
#pragma unroll
                for (int i = 0; i < 4; i++) dst[tid + i * NTHREADS] = src[tid + i * NTHREADS];
                FENCE_ASYNC();
                __syncthreads();
            }

            // ---- issue GEMM1 split into two N=64 halves (TS: A = X in TMEM) ----
            if (wid == 0) {
                if (elect_one_pred()) {
                    TCGEN05_FENCE_AFTER();
#pragma unroll
                    for (int g = 0; g < 8; g++) {
                        uint32_t off  = (g & 3) * 2 + (g >> 2) * 1024;
                        uint32_t acol = g * 8;
                        mma_f16_ts_n64(tmem_base + T_D1, tmem_base + T_XHI + acol, bW1 + off, g > 0);
                    }
                    TCGEN05_COMMIT(smem_base + MBAR1A_OFF);
#pragma unroll
                    for (int g = 0; g < 8; g++) {
                        uint32_t off  = (g & 3) * 2 + (g >> 2) * 1024 + 512;  // +8192 B: rows 64-127
                        uint32_t acol = g * 8;
                        mma_f16_ts_n64(tmem_base + T_D1 + 64, tmem_base + T_XHI + acol, bW1 + off, g > 0);
                    }
                    TCGEN05_COMMIT(smem_base + MBAR1B_OFF);
                }
            }

            // ---- wait GEMM2(c-1) (frees W2 buffer), then async-copy W2(c) ----
            if (g2_pending) { MBARRIER_WAIT_PARITY(smem_base + MBAR2_OFF, p2); p2 ^= 1; g2_pending = 0; }
            if (tid == 0) {
                MBARRIER_EXPECT_TX(smem_base + MBW2_OFF, 32768);
                BULK_COPY_G2S(smem_base + W2_OFF, g_w2img + c * 32768, 32768, smem_base + MBW2_OFF);
            }

            // ---- wait only THIS warp's G1 half; H-epi(a) overlaps G1b drain ----
            MBARRIER_WAIT_PARITY(my_g1_bar, p1); p1 ^= 1;
            TCGEN05_FENCE_AFTER();
            {
                uint32_t r32[32];
                TCGEN05_LD_X32(r32, tmem_base + T_D1 + c0);
                TCGEN05_WAIT_LD();
                const float* bptr = b1e_s + c * 128 + c0;
#pragma unroll
                for (int gi = 0; gi < 4; gi++) {
                    uint32_t hv[4];
#pragma unroll
                    for (int p = 0; p < 4; p++) {
                        int i0 = gi * 8 + p * 2;
                        float h0 = fast_tanh(__uint_as_float(r32[i0])     + bptr[i0]);
                        float h1 = fast_tanh(__uint_as_float(r32[i0 + 1]) + bptr[i0 + 1]);
                        hv[p] = fp16_pack2(h0, h1);
                    }
                    int k = c0 + gi * 8;
                    int sw = img_off(row, k);
                    asm volatile("st.shared.v4.b32 [%0], {%1, %2, %3, %4};"
                        :: "r"(smem_base + H_OFF + sw), "r"(hv[0]), "r"(hv[1]), "r"(hv[2]), "r"(hv[3]) : "memory");
                }
            }
            FENCE_ASYNC();
            __syncthreads();   // H visible; D1 fully consumed (both halves)

            // ---- W2(c) copy complete? (overlapped G1 drain + H-epi) ----
            MBARRIER_WAIT_PARITY(smem_base + MBW2_OFF, pw2); pw2 ^= 1;

            // ---- issue GEMM2 (SS, N=128), accumulate U ----
            if (wid == 0) {
                if (elect_one_pred()) {
                    TCGEN05_FENCE_AFTER();
#pragma unroll
                    for (int g = 0; g < 8; g++) {
                        uint32_t off = (g & 3) * 2 + (g >> 2) * 1024;
                        uint32_t en0 = (c > 0) || (g > 0);
                        mma_f16_ss(tmem_base + T_U, aHhi + off, bW2 + off, en0);
                    }
                    TCGEN05_COMMIT(smem_base + MBAR2_OFF);
                }
            }
            g2_pending = 1;
        }

        // ================= step epilogue =================
        // prefetch noise (fully coalesced) while GEMM2(3) drains
        float4 npref[8];
        {
            const float4* nb4 = (const float4*)(noise + (size_t)tile * 128 * DIMX);
#pragma unroll
            for (int i = 0; i < 8; i++) npref[i] = nb4[tid + i * NTHREADS];
        }

        MBARRIER_WAIT_PARITY(smem_base + MBAR2_OFF, p2); p2 ^= 1; g2_pending = 0;
        TCGEN05_FENCE_AFTER();

        // stage noise into rotated pitch-128 tile over the H region (dead now).
        // Per-element NB_IDX (rotated column wraps within the row).
        {
            float* ns = (float*)(sm + NOISE_OFF);
#pragma unroll
            for (int i = 0; i < 8; i++) {
                int idx = tid + i * NTHREADS;
                int r = idx >> 5, cc = (idx & 31) * 4;
                ns[NB_IDX(r, cc)]     = npref[i].x;
                ns[NB_IDX(r, cc + 1)] = npref[i].y;
                ns[NB_IDX(r, cc + 2)] = npref[i].z;
                ns[NB_IDX(r, cc + 3)] = npref[i].w;
            }
        }
        __syncthreads();

        // SDE math in LDTM layout; results to OUTBUF (dedicated, rotated) + TMEM
        {
            const float* ns = (const float*)(sm + NOISE_OFF);
            float* ob = (float*)(sm + OUTBUF_OFF);
            float udw = 0.0f, en = 0.0f;
#pragma unroll
            for (int h = 0; h < 2; h++) {
                uint32_t uv[16], yv[16];
                TCGEN05_LD_X16(uv, tmem_base + T_U + c0 + h * 16);
                TCGEN05_LD_X16(yv, tmem_base + T_Y + c0 + h * 16);
                TCGEN05_WAIT_LD();
                uint32_t hv[8];
#pragma unroll
                for (int i2 = 0; i2 < 8; i2++) {
                    float yn2[2];
#pragma unroll
                    for (int q = 0; q < 2; q++) {
                        int i = i2 * 2 + q;
                        int col = c0 + h * 16 + i;
                        float u  = __uint_as_float(uv[i]) + b2_s[col];
                        float y  = __uint_as_float(yv[i]);
                        float nz = ns[NB_IDX(row, col)];
                        float ynew = y + (u - y) * dt + sq * nz;
                        udw += u * nz;
                        en  += u * u;
                        ob[OB_IDX(row, col)] = ynew;
                        yv[i] = __float_as_uint(ynew);
                        yn2[q] = ynew;
                    }
                    hv[i2] = fp16_pack2(yn2[0], yn2[1]);
                }
                TCGEN05_ST_X16(tmem_base + T_Y + c0 + h * 16 + st_warp_off, yv);
                TCGEN05_ST_X8(tmem_base + T_XHI + cg * 16 + h * 8 + st_warp_off, hv);
            }
            TCGEN05_WAIT_ST();
            TCGEN05_FENCE_BEFORE();

            ((float*)(sm + PUDW_OFF))[row * 4 + cg] = udw;
            ((float*)(sm + PEN_OFF))[row * 4 + cg]  = en;
        }
        __syncthreads();

        // kick next step's W1(0) copy — overlaps aug + y write-out below.
        // Safe: noise fully consumed; W1 region untouched by noise anyway.
        if (s < NSTEPS_ - 1 && tid == 0) {
            MBARRIER_EXPECT_TX(smem_base + MBW1_OFF, 32768);
            BULK_COPY_G2S(smem_base + W1_OFF, g_w1img, 32768, smem_base + MBW1_OFF);
        }

        // aug channels (cg0 threads own one row each; running state in regs)
        if (cg == 0) {
            const float* pu = (const float*)(sm + PUDW_OFF) + row * 4;
            const float* pe = (const float*)(sm + PEN_OFF) + row * 4;
            float udw = pu[0] + pu[1] + pu[2] + pu[3];
            float en  = pe[0] + pe[1] + pe[2] + pe[3];
            aug01 += udw * sq;
            aug2  += 0.5f * en * dt;
            float* oa = next + ((size_t)tile * 128 + row) * OUTC + DIMX;
            oa[0] = aug01;
            oa[1] = aug01;
            oa[2] = aug2;
        }

        // coalesced y writes from rotated OUTBUF
        {
            const float* ob = (const float*)(sm + OUTBUF_OFF);
            float* nb = next + (size_t)tile * 128 * OUTC;
#pragma unroll
            for (int i = 0; i < 32; i++) {
                int e = tid + i * NTHREADS;
                int r = e >> 7, cc = e & 127;
                nb[(size_t)r * OUTC + cc] = ob[OB_IDX(r, cc)];
            }
        }
        __syncthreads();   // scratch regions reused next step
    }

    if (tid == 0) {
        MBARRIER_INVAL(smem_base + MBAR1A_OFF);
        MBARRIER_INVAL(smem_base + MBAR1B_OFF);
        MBARRIER_INVAL(smem_base + MBAR2_OFF);
        MBARRIER_INVAL(smem_base + MBW2_OFF);
        MBARRIER_INVAL(smem_base + MBW1_OFF);
    }
    __syncthreads();
    if (wid == 0) TCGEN05_DEALLOC(tmem_base, 512);

#else  // ======================= SIMT f32x2 fallback =======================
    extern __shared__ float smf[];
    float* XT  = smf + F_XT;
    float* W1s = smf + F_W1;
    float* HT  = smf + F_HT;
    float* W2s = smf + F_W2;
    float* b1s = smf + F_B1;
    float* b2s = smf + F_B2;

    const int tid   = threadIdx.x;
    const int tx    = tid & 31;
    const int wid   = tid >> 5;
    const int rbase = wid * 8;
    const int row0  = blockIdx.x * 128;

    for (int i = tid; i < HID; i += NTHREADS)  b1s[i] = b1[i];
    for (int i = tid; i < DIMX; i += NTHREADS) b2s[i] = b2[i];

    for (int s = 0; s < NSTEPS_; s++) {
        const float* prev  = out + (size_t)s * BATCH_ * OUTC;
        float*       next  = out + (size_t)(s + 1) * BATCH_ * OUTC;
        const float* noise = noises + (size_t)s * BATCH_ * DIMX;
        const float tp = ts[s];
        const float dt = ts[s + 1] - tp;
        const float sq = sqrtf(dt);

        __syncthreads();
        for (int idx = tid; idx < 128 * DIMX; idx += NTHREADS) {
            int r = idx >> 7, c = idx & 127;
            XT[c * F_PITCH + r] = prev[(size_t)(row0 + r) * OUTC + c];
        }
        for (int r = tid; r < 128; r += NTHREADS) XT[DIMX * F_PITCH + r] = tp;
        __syncthreads();

        u64 Uacc[8][2];
        {
            u64 pr0 = pack2f(b2s[tx], b2s[tx + 32]);
            u64 pr1 = pack2f(b2s[tx + 64], b2s[tx + 96]);
#pragma unroll
            for (int j = 0; j < 8; j++) { Uacc[j][0] = pr0; Uacc[j][1] = pr1; }
        }

        for (int ch = 0; ch < 8; ch++) {
            if (ch) __syncthreads();
            for (int idx = tid; idx < 129 * 16; idx += NTHREADS) {
                int k = idx >> 4, c4 = idx & 15;
                ((float4*)W1s)[k * 16 + c4] =
                    *(const float4*)&W1[(size_t)k * HID + ch * 64 + c4 * 4];
            }
            for (int idx = tid; idx < 64 * 32; idx += NTHREADS) {
                ((float4*)W2s)[idx] =
                    *(const float4*)&W2[(size_t)(ch * 64) * DIMX + idx * 4];
            }
            __syncthreads();

            u64 Hacc[8];
#pragma unroll
            for (int j = 0; j < 8; j++) Hacc[j] = 0ull;

#pragma unroll 2
            for (int k = 0; k < 129; k++) {
                const float* xrow = XT + k * F_PITCH + rbase;
                float4 xa = *(const float4*)(xrow);
                float4 xb = *(const float4*)(xrow + 4);
                u64 wp = pack2f(W1s[k * 64 + tx], W1s[k * 64 + tx + 32]);
                FMMA8x1(Hacc, xa, xb, wp);
            }
            {
                float bA = b1s[ch * 64 + tx];
                float bB = b1s[ch * 64 + tx + 32];
#pragma unroll
                for (int j = 0; j < 8; j++) {
                    float2 h = unpack2f(Hacc[j]);
                    int r = rbase + j;
                    HT[(tx)      * F_PITCH + r] = tanhf(h.x + bA);
                    HT[(tx + 32) * F_PITCH + r] = tanhf(h.y + bB);
                }
            }
            __syncthreads();

#pragma unroll 2
            for (int k = 0; k < 64; k++) {
                const float* hrow = HT + k * F_PITCH + rbase;
                float4 ha = *(const float4*)(hrow);
                float4 hb = *(const float4*)(hrow + 4);
                const float* wrow = W2s + k * DIMX + tx;
                u64 wp0 = pack2f(wrow[0], wrow[32]);
                u64 wp1 = pack2f(wrow[64], wrow[96]);
                FMMA8x2(Uacc, ha, hb, wp0, wp1);
            }
        }

#pragma unroll
        for (int j = 0; j < 8; j++) {
            int r = rbase + j;
            size_t grow = (size_t)(row0 + r);
            float2 u0 = unpack2f(Uacc[j][0]);
            float2 u1 = unpack2f(Uacc[j][1]);

            float yA = XT[(tx)      * F_PITCH + r];
            float yB = XT[(tx + 32) * F_PITCH + r];
            float yC = XT[(tx + 64) * F_PITCH + r];
            float yD = XT[(tx + 96) * F_PITCH + r];

            const float* np = noise + grow * DIMX;
            float nA = np[tx], nB = np[tx + 32], nC = np[tx + 64], nD = np[tx + 96];

            float* op = next + grow * OUTC;
            op[tx]      = yA + (u0.x - yA) * dt + sq * nA;
            op[tx + 32] = yB + (u0.y - yB) * dt + sq * nB;
            op[tx + 64] = yC + (u1.x - yC) * dt + sq * nC;
            op[tx + 96] = yD + (u1.y - yD) * dt + sq * nD;

            float udw = u0.x * nA + u0.y * nB + u1.x * nC + u1.y * nD;
            float en  = u0.x * u0.x + u0.y * u0.y + u1.x * u1.x + u1.y * u1.y;
#pragma unroll
            for (int off = 16; off; off >>= 1) {
                udw += __shfl_xor_sync(0xffffffffu, udw, off);
                en  += __shfl_xor_sync(0xffffffffu, en, off);
            }
            if (tx == 0) {
                const float* pp = prev + grow * OUTC + DIMX;
                float incr = udw * sq;
                op[DIMX]     = pp[0] + incr;
                op[DIMX + 1] = pp[1] + incr;
                op[DIMX + 2] = pp[2] + 0.5f * en * dt;
            }
        }
    }
#endif
}

extern "C" void kernel_launch(void* const* d_in, const int* in_sizes, int n_in,
                              void* d_out, int out_size)
{
    const float* y0     = (const float*)d_in[0];
    const float* W1     = (const float*)d_in[1];
    const float* b1     = (const float*)d_in[2];
    const float* W2     = (const float*)d_in[3];
    const float* b2     = (const float*)d_in[4];
    const float* noises = (const float*)d_in[5];
    const float* ts     = (const float*)d_in[6];
    float* out = (float*)d_out;

    cudaFuncSetAttribute(main_kernel,
                         cudaFuncAttributeMaxDynamicSharedMemorySize, SMEM_BYTES);

    size_t traj_elems = (size_t)(NSTEPS_ + 1) * BATCH_ * OUTC;
    int write_ts = ((size_t)out_size >= traj_elems + (NSTEPS_ + 1)) ? 1 : 0;

    prep_kernel<<<(131072 + NSTEPS_ * HID + 511) / 512, 512>>>(W1, b1, W2, ts);
    init_kernel<<<(BATCH_ * OUTC) / 512, 512>>>(y0, ts, out, write_ts);
    main_kernel<<<NTILES, NTHREADS, SMEM_BYTES>>>(out, y0, noises, W1, b1, W2, b2, ts);
}